// round 13
// baseline (speedup 1.0000x reference)
#include <cuda_runtime.h>
#include <cuda_bf16.h>
#include <cstdint>

#define NFC   64
#define HWS   64
#define PSZ   8
#define NB    4
#define NT    16
#define NIMG  64      // NB*NT
#define TOK   1024    // NT * 64 patches
#define DIMD  4096    // NFC * PSZ * PSZ

// ---------------- scratch (static device globals; no allocation) -------------
__device__ __align__(128) __nv_bfloat16 g_Qh[NB][TOK][DIMD];
__device__ __align__(128) __nv_bfloat16 g_Ql[NB][TOK][DIMD];
__device__ __align__(128) __nv_bfloat16 g_Kh[NB][TOK][DIMD];
__device__ __align__(128) __nv_bfloat16 g_Kl[NB][TOK][DIMD];
__device__ __align__(128) __nv_bfloat16 g_Vth[NB][DIMD][TOK];
__device__ __align__(128) __nv_bfloat16 g_Vtl[NB][DIMD][TOK];
__device__ __align__(128) float         g_S [NB][TOK][TOK];
__device__ __align__(128) __nv_bfloat16 g_Ph[NB][TOK][TOK];
__device__ __align__(128) __nv_bfloat16 g_Pl[NB][TOK][TOK];
__device__ __align__(128) float g_feat[NIMG][NFC][HWS][HWS];
// conv weights as [tap][oc][ic] bf16 hi/lo, pre-swizzled for ldmatrix
__device__ __align__(128) __nv_bfloat16 g_Wvh[9 * 4096];
__device__ __align__(128) __nv_bfloat16 g_Wvl[9 * 4096];
__device__ __align__(128) __nv_bfloat16 g_Wch[9 * 4096];
__device__ __align__(128) __nv_bfloat16 g_Wcl[9 * 4096];

// ---------------- side stream + events (created once, before main) -----------
struct SideStream {
    cudaStream_t s1;
    cudaEvent_t  e0, e1;
    SideStream() {
        cudaStreamCreateWithFlags(&s1, cudaStreamNonBlocking);
        cudaEventCreateWithFlags(&e0, cudaEventDisableTiming);
        cudaEventCreateWithFlags(&e1, cudaEventDisableTiming);
    }
};
static SideStream g_ss;

// ======================= helpers ==============================================
__device__ __forceinline__ uint32_t smem_u32(const void* p) {
    uint32_t a;
    asm("{ .reg .u64 t; cvta.to.shared.u64 t, %1; cvt.u32.u64 %0, t; }"
        : "=r"(a) : "l"(p));
    return a;
}
__device__ __forceinline__ void cpa16(uint32_t dst, const void* src) {
    asm volatile("cp.async.cg.shared.global [%0], [%1], 16;"
                 :: "r"(dst), "l"(__cvta_generic_to_global(src)));
}
__device__ __forceinline__ void cpa_commit() { asm volatile("cp.async.commit_group;" ::: "memory"); }
__device__ __forceinline__ void cpa_wait1()  { asm volatile("cp.async.wait_group 1;" ::: "memory"); }
__device__ __forceinline__ void cpa_wait0()  { asm volatile("cp.async.wait_group 0;" ::: "memory"); }

__device__ __forceinline__ void mma16816(float* c, const uint32_t* a, const uint32_t* b) {
    asm volatile(
        "mma.sync.aligned.m16n8k16.row.col.f32.bf16.bf16.f32 "
        "{%0,%1,%2,%3}, {%4,%5,%6,%7}, {%8,%9}, {%0,%1,%2,%3};"
        : "+f"(c[0]), "+f"(c[1]), "+f"(c[2]), "+f"(c[3])
        : "r"(a[0]), "r"(a[1]), "r"(a[2]), "r"(a[3]), "r"(b[0]), "r"(b[1]));
}
__device__ __forceinline__ void ldsm4(uint32_t* r, uint32_t addr) {
    asm volatile("ldmatrix.sync.aligned.m8n8.x4.shared.b16 {%0,%1,%2,%3}, [%4];"
                 : "=r"(r[0]), "=r"(r[1]), "=r"(r[2]), "=r"(r[3]) : "r"(addr));
}

// ---------------- kernel 0: prep conv weights (hi/lo, swizzled) ---------------
__global__ void prep_w_kernel(const float* __restrict__ vw,
                              const float* __restrict__ cw) {
    int idx = blockIdx.x * blockDim.x + threadIdx.x;
    if (idx < 9 * 64 * 64) {
        int t   = idx >> 12;
        int rem = idx & 4095;
        int oc  = rem >> 6;
        int ic  = rem & 63;
        int di  = t * 4096 + oc * 64 + (ic ^ ((oc & 7) << 3));
        float v = vw[oc * 576 + ic * 9 + t];
        __nv_bfloat16 h = __float2bfloat16(v);
        g_Wvh[di] = h;
        g_Wvl[di] = __float2bfloat16(v - __bfloat162float(h));
        v = cw[oc * 576 + ic * 9 + t];
        h = __float2bfloat16(v);
        g_Wch[di] = h;
        g_Wcl[di] = __float2bfloat16(v - __bfloat162float(h));
    }
}

// ---------------- kernel: depthwise q/k conv -> token-layout hi/lo bf16 -------
__global__ __launch_bounds__(512) void dwqk_kernel(
    const float* __restrict__ x,
    const float* __restrict__ qw, const float* __restrict__ qb,
    const float* __restrict__ kw, const float* __restrict__ kb)
{
    extern __shared__ float s[];          // [64][10][66]
    const int img   = blockIdx.x;
    const int ytile = blockIdx.y;
    const int y0    = ytile * 8;
    const int bb    = img >> 4;
    const int tt    = img & 15;
    const int tid   = threadIdx.x;
    const float* xim = x + (size_t)img * NFC * HWS * HWS;

    for (int idx = tid; idx < 64 * 10 * 66; idx += 512) {
        int c  = idx / 660;
        int rr = idx - c * 660;
        int yy = rr / 66;
        int xx = rr - yy * 66;
        int gy = y0 - 1 + yy;
        int gx = xx - 1;
        float v = 0.f;
        if (gy >= 0 && gy < 64 && gx >= 0 && gx < 64)
            v = xim[c * 4096 + gy * 64 + gx];
        s[idx] = v;
    }
    __syncthreads();

    const int c  = tid >> 3;
    const int xb = tid & 7;
    const int x0 = xb * 8;
    const int tok = tt * 64 + ytile * 8 + xb;
    float wq[9], wk[9];
    #pragma unroll
    for (int i = 0; i < 9; i++) { wq[i] = qw[c * 9 + i]; wk[i] = kw[c * 9 + i]; }
    const float bq = qb[c], bk = kb[c];
    const float* sc = s + c * 660;

    #pragma unroll
    for (int y = 0; y < 8; y++) {
        float r0[10], r1[10], r2[10];
        #pragma unroll
        for (int j = 0; j < 10; j++) {
            r0[j] = sc[(y + 0) * 66 + x0 + j];
            r1[j] = sc[(y + 1) * 66 + x0 + j];
            r2[j] = sc[(y + 2) * 66 + x0 + j];
        }
        uint32_t qh4[4], ql4[4], kh4[4], kl4[4];
        #pragma unroll
        for (int pp = 0; pp < 4; pp++) {
            float aq[2], ak[2];
            #pragma unroll
            for (int e = 0; e < 2; e++) {
                int xx = pp * 2 + e;
                float q = bq, k = bk;
                #pragma unroll
                for (int kx = 0; kx < 3; kx++) {
                    q = fmaf(r0[xx + kx], wq[kx], q);
                    q = fmaf(r1[xx + kx], wq[3 + kx], q);
                    q = fmaf(r2[xx + kx], wq[6 + kx], q);
                    k = fmaf(r0[xx + kx], wk[kx], k);
                    k = fmaf(r1[xx + kx], wk[3 + kx], k);
                    k = fmaf(r2[xx + kx], wk[6 + kx], k);
                }
                aq[e] = q; ak[e] = k;
            }
            __nv_bfloat162 h2 = __floats2bfloat162_rn(aq[0], aq[1]);
            qh4[pp] = *(uint32_t*)&h2;
            __nv_bfloat162 l2 = __floats2bfloat162_rn(
                aq[0] - __bfloat162float(__low2bfloat16(h2)),
                aq[1] - __bfloat162float(__high2bfloat16(h2)));
            ql4[pp] = *(uint32_t*)&l2;
            h2 = __floats2bfloat162_rn(ak[0], ak[1]);
            kh4[pp] = *(uint32_t*)&h2;
            l2 = __floats2bfloat162_rn(
                ak[0] - __bfloat162float(__low2bfloat16(h2)),
                ak[1] - __bfloat162float(__high2bfloat16(h2)));
            kl4[pp] = *(uint32_t*)&l2;
        }
        const int d = c * 64 + y * 8;
        *(uint4*)&g_Qh[bb][tok][d] = make_uint4(qh4[0], qh4[1], qh4[2], qh4[3]);
        *(uint4*)&g_Ql[bb][tok][d] = make_uint4(ql4[0], ql4[1], ql4[2], ql4[3]);
        *(uint4*)&g_Kh[bb][tok][d] = make_uint4(kh4[0], kh4[1], kh4[2], kh4[3]);
        *(uint4*)&g_Kl[bb][tok][d] = make_uint4(kl4[0], kl4[1], kl4[2], kl4[3]);
    }
}

// ---------------- implicit-GEMM conv (tensor cores), both convs ---------------
// mode 0 (V): src = x image; writes Vt hi/lo (transposed, +vb)
// mode 1 (C): src = g_feat; writes out = conv + cb + residual x
#define CG_XH    0u
#define CG_XL    84480u
#define CG_W     168960u       // + stage*16384 ; hi at +0, lo at +8192
#define CG_SMEM  201728
#define DB_PITCH 520

__global__ __launch_bounds__(512) void conv_gemm_kernel(
    int mode,
    const float* __restrict__ xin,
    const float* __restrict__ bias,
    float* __restrict__ out)
{
    extern __shared__ char sm[];
    const uint32_t sb = smem_u32(sm);
    const int img   = blockIdx.x;
    const int ytile = blockIdx.y;
    const int y0    = ytile * 8;
    const int tid   = threadIdx.x;
    const int wid   = tid >> 5;
    const int lane  = tid & 31;
    const int lrow  = lane & 15;
    const int lhi   = lane >> 4;
    const int wy    = wid >> 1;          // warp y-row (0..7)
    const int wx0   = (wid & 1) * 32;    // warp x base

    const float* src = (mode == 0) ? (xin + (size_t)img * NFC * HWS * HWS)
                                   : &g_feat[img][0][0][0];
    const __nv_bfloat16* Wh = (mode == 0) ? g_Wvh : g_Wch;
    const __nv_bfloat16* Wl = (mode == 0) ? g_Wvl : g_Wcl;

    // prefetch weight taps 0,1 (cp.async groups)
    #pragma unroll
    for (int s = 0; s < 2; s++) {
        for (int u = tid; u < 1024; u += 512) {
            int term = u >> 9, off = (u & 511) * 16;
            const char* gsrc = (const char*)((term ? Wl : Wh) + s * 4096) + off;
            cpa16(sb + CG_W + (uint32_t)s * 16384u + (uint32_t)(term * 8192 + off), gsrc);
        }
        cpa_commit();
    }

    // load X halo tile -> bf16 hi/lo swizzled [r][c]
    for (int base = 0; base < 42240; base += 512) {
        int idx = base + tid;
        if (idx < 42240) {
            int c  = idx / 660;
            int r  = idx - c * 660;
            int yy = r / 66;
            int xx = r - yy * 66;
            int gy = y0 - 1 + yy, gx = xx - 1;
            float v = 0.f;
            if (gy >= 0 && gy < 64 && gx >= 0 && gx < 64)
                v = src[c * 4096 + gy * 64 + gx];
            __nv_bfloat16 h = __float2bfloat16(v);
            __nv_bfloat16 l = __float2bfloat16(v - __bfloat162float(h));
            uint32_t o = (uint32_t)(r * 128 + 2 * (c ^ ((r & 7) << 3)));
            *(__nv_bfloat16*)(sm + CG_XH + o) = h;
            *(__nv_bfloat16*)(sm + CG_XL + o) = l;
        }
    }
    __syncthreads();

    // ---- main MMA loop over 9 taps ----
    float acc[2][8][4];
    #pragma unroll
    for (int mt = 0; mt < 2; mt++)
        #pragma unroll
        for (int nt = 0; nt < 8; nt++)
            #pragma unroll
            for (int q = 0; q < 4; q++) acc[mt][nt][q] = 0.f;

    for (int tap = 0; tap < 9; tap++) {
        const int ky = tap / 3;
        const int kx = tap - ky * 3;
        if (tap + 1 < 9) cpa_wait1(); else cpa_wait0();
        __syncthreads();
        const uint32_t wbuf = sb + CG_W + (uint32_t)(tap & 1) * 16384u;
        const int rbase = (wy + ky) * 66 + wx0 + lrow + kx;

        #pragma unroll
        for (int ks = 0; ks < 4; ks++) {
            const uint32_t cofs = (uint32_t)(ks * 32 + lhi * 16);
            uint32_t a[2][4], al[2][4], bh[4][4], bl[4][4];
            // issue ALL fragment loads up front (independent registers)
            #pragma unroll
            for (int mt = 0; mt < 2; mt++) {
                int r = rbase + mt * 16;
                ldsm4(a[mt], sb + CG_XH + (uint32_t)(r * 128)
                             + (cofs ^ ((uint32_t)(r & 7) << 4)));
            }
            #pragma unroll
            for (int np = 0; np < 4; np++) {
                int o = np * 16 + lrow;
                ldsm4(bh[np], wbuf + (uint32_t)(o * 128)
                              + (cofs ^ ((uint32_t)(o & 7) << 4)));
            }
            #pragma unroll
            for (int np = 0; np < 4; np++) {
                int o = np * 16 + lrow;
                ldsm4(bl[np], wbuf + 8192u + (uint32_t)(o * 128)
                              + (cofs ^ ((uint32_t)(o & 7) << 4)));
            }
            #pragma unroll
            for (int mt = 0; mt < 2; mt++) {
                int r = rbase + mt * 16;
                ldsm4(al[mt], sb + CG_XL + (uint32_t)(r * 128)
                              + (cofs ^ ((uint32_t)(r & 7) << 4)));
            }
            // MMA groups: hh, hl, lh
            #pragma unroll
            for (int mt = 0; mt < 2; mt++)
                #pragma unroll
                for (int nt = 0; nt < 8; nt++) {
                    uint32_t bf[2] = { bh[nt >> 1][nt & 1], bh[nt >> 1][(nt & 1) + 2] };
                    mma16816(acc[mt][nt], a[mt], bf);
                }
            #pragma unroll
            for (int mt = 0; mt < 2; mt++)
                #pragma unroll
                for (int nt = 0; nt < 8; nt++) {
                    uint32_t bf[2] = { bl[nt >> 1][nt & 1], bl[nt >> 1][(nt & 1) + 2] };
                    mma16816(acc[mt][nt], a[mt], bf);
                }
            #pragma unroll
            for (int mt = 0; mt < 2; mt++)
                #pragma unroll
                for (int nt = 0; nt < 8; nt++) {
                    uint32_t bf[2] = { bh[nt >> 1][nt & 1], bh[nt >> 1][(nt & 1) + 2] };
                    mma16816(acc[mt][nt], al[mt], bf);
                }
        }
        __syncthreads();
        if (tap + 2 < 9) {
            const int tp = tap + 2;
            const uint32_t dbuf = sb + CG_W + (uint32_t)(tp & 1) * 16384u;
            for (int u = tid; u < 1024; u += 512) {
                int term = u >> 9, off = (u & 511) * 16;
                const char* gsrc = (const char*)((term ? Wl : Wh) + tp * 4096) + off;
                cpa16(dbuf + (uint32_t)(term * 8192 + off), gsrc);
            }
            cpa_commit();
        }
    }

    // ---- stage D through smem (X area is dead now), then coalesced writeout ---
    float* Dbuf = (float*)sm;
    const int g  = lane >> 2;
    const int tq = lane & 3;
    #pragma unroll
    for (int mt = 0; mt < 2; mt++)
        #pragma unroll
        for (int rr = 0; rr < 2; rr++) {
            int px = wy * 64 + wx0 + mt * 16 + g + rr * 8;
            #pragma unroll
            for (int nt = 0; nt < 8; nt++) {
                int oc = nt * 8 + tq * 2;
                Dbuf[oc * DB_PITCH + px]       = acc[mt][nt][rr * 2];
                Dbuf[(oc + 1) * DB_PITCH + px] = acc[mt][nt][rr * 2 + 1];
            }
        }
    __syncthreads();

    if (mode == 0) {
        // fused transpose + hi/lo split: write Vt[d][tok] directly
        const int bb = img >> 4, tt = img & 15;
        const int tokbase = tt * 64 + ytile * 8;
        for (int e = tid; e < 32768; e += 512) {
            int d  = e >> 3, xb = e & 7;
            int oc = d >> 6, y = (d >> 3) & 7, xa = d & 7;
            float v = Dbuf[oc * DB_PITCH + y * 64 + xb * 8 + xa] + bias[oc];
            __nv_bfloat16 h = __float2bfloat16(v);
            g_Vth[bb][d][tokbase + xb] = h;
            g_Vtl[bb][d][tokbase + xb] = __float2bfloat16(v - __bfloat162float(h));
        }
    } else {
        for (int e = tid; e < 32768; e += 512) {
            int oc = e >> 9, y = (e >> 6) & 7, xx = e & 63;
            int gb = ((img * 64 + oc) * 64 + y0 + y) * 64 + xx;
            out[gb] = Dbuf[oc * DB_PITCH + y * 64 + xx] + bias[oc] + xin[gb];
        }
    }
}

// ---------------- mma.sync GEMM (both attention GEMMs) -------------------------
// CTA tile 128x128, warp tile 64x32 (2x4 warp grid), K-chunk 32.
#define OFF_AH   0u
#define OFF_AL   10240u                 // 128*80
#define OFF_BH   20480u
#define OFF_BL   30720u
#define STAGE_B  40960u

__device__ __forceinline__ void load_chunk32(
    uint32_t sb, int tid,
    const __nv_bfloat16* Ah, const __nv_bfloat16* Al, int i0,
    const __nv_bfloat16* Bh, const __nv_bfloat16* Bl, int j0,
    int ld, int k0)
{
    #pragma unroll
    for (int u = tid; u < 2048; u += 256) {
        int part = u >> 9;               // 0:Ah 1:Al 2:Bh 3:Bl
        int idx  = u & 511;              // 128 rows * 4 16B-chunks
        int r = idx >> 2, c = idx & 3;
        const __nv_bfloat16* src;
        if      (part == 0) src = Ah + (size_t)(i0 + r) * ld + k0 + c * 8;
        else if (part == 1) src = Al + (size_t)(i0 + r) * ld + k0 + c * 8;
        else if (part == 2) src = Bh + (size_t)(j0 + r) * ld + k0 + c * 8;
        else                src = Bl + (size_t)(j0 + r) * ld + k0 + c * 8;
        cpa16(sb + (uint32_t)part * 10240u + (uint32_t)(r * 80 + c * 16), src);
    }
    cpa_commit();
}

__global__ __launch_bounds__(256, 2) void gemm_mma_kernel(int mode)
{
    extern __shared__ char dsm[];
    const int tid  = threadIdx.x;
    const int wid  = tid >> 5;
    const int lane = tid & 31;
    const int g    = lane >> 2;          // 0..7
    const int t    = lane & 3;           // 0..3
    const int b    = blockIdx.z;
    const int i0   = blockIdx.y * 128;
    const int j0   = blockIdx.x * 128;
    const int wm   = (wid >> 2) * 64;
    const int wn   = (wid & 3) * 32;
    const int lrow = lane & 15;
    const int lk   = (lane >> 4) << 3;

    const __nv_bfloat16 *Ah, *Al, *Bh, *Bl;
    int ld, nch;
    if (mode == 0) {
        Ah = &g_Qh[b][0][0]; Al = &g_Ql[b][0][0];
        Bh = &g_Kh[b][0][0]; Bl = &g_Kl[b][0][0];
        ld = DIMD; nch = DIMD / 32;
    } else {
        Ah = &g_Ph[b][0][0]; Al = &g_Pl[b][0][0];
        Bh = &g_Vth[b][0][0]; Bl = &g_Vtl[b][0][0];
        ld = TOK; nch = TOK / 32;
    }

    const uint32_t sbase = smem_u32(dsm);
    float acc[4][4][4];
    #pragma unroll
    for (int mt = 0; mt < 4; mt++)
        #pragma unroll
        for (int nt = 0; nt < 4; nt++)
            #pragma unroll
            for (int q = 0; q < 4; q++) acc[mt][nt][q] = 0.f;

    load_chunk32(sbase,           tid, Ah, Al, i0, Bh, Bl, j0, ld, 0);
    load_chunk32(sbase + STAGE_B, tid, Ah, Al, i0, Bh, Bl, j0, ld, 32);

    for (int it = 0; it < nch; ++it) {
        const int p = it & 1;
        const uint32_t st = sbase + (uint32_t)p * STAGE_B;
        if (it + 1 < nch) cpa_wait1(); else cpa_wait0();
        __syncthreads();

        #pragma unroll
        for (int ks = 0; ks < 32; ks += 16) {
            uint32_t a[4][4], al[4][4], bh2[2][4], bl2[2][4];
            const uint32_t cofs = (uint32_t)((ks + lk) * 2);
            // issue ALL fragment loads up front (independent registers)
            #pragma unroll
            for (int mt = 0; mt < 4; mt++)
                ldsm4(a[mt], st + OFF_AH + (uint32_t)((wm + mt * 16 + lrow) * 80) + cofs);
            #pragma unroll
            for (int ntp = 0; ntp < 2; ntp++)
                ldsm4(bh2[ntp], st + OFF_BH + (uint32_t)((wn + ntp * 16 + lrow) * 80) + cofs);
            #pragma unroll
            for (int ntp = 0; ntp < 2; ntp++)
                ldsm4(bl2[ntp], st + OFF_BL + (uint32_t)((wn + ntp * 16 + lrow) * 80) + cofs);
            #pragma unroll
            for (int mt = 0; mt < 4; mt++)
                ldsm4(al[mt], st + OFF_AL + (uint32_t)((wm + mt * 16 + lrow) * 80) + cofs);
            // MMA groups: hh, hl, lh
            #pragma unroll
            for (int mt = 0; mt < 4; mt++)
                #pragma unroll
                for (int nt = 0; nt < 4; nt++) {
                    uint32_t bf[2] = { bh2[nt >> 1][nt & 1], bh2[nt >> 1][(nt & 1) + 2] };
                    mma16816(acc[mt][nt], a[mt], bf);
                }
            #pragma unroll
            for (int mt = 0; mt < 4; mt++)
                #pragma unroll
                for (int nt = 0; nt < 4; nt++) {
                    uint32_t bf[2] = { bl2[nt >> 1][nt & 1], bl2[nt >> 1][(nt & 1) + 2] };
                    mma16816(acc[mt][nt], a[mt], bf);
                }
            #pragma unroll
            for (int mt = 0; mt < 4; mt++)
                #pragma unroll
                for (int nt = 0; nt < 4; nt++) {
                    uint32_t bf[2] = { bh2[nt >> 1][nt & 1], bh2[nt >> 1][(nt & 1) + 2] };
                    mma16816(acc[mt][nt], al[mt], bf);
                }
        }
        __syncthreads();
        if (it + 2 < nch)
            load_chunk32(sbase + (uint32_t)p * STAGE_B, tid,
                         Ah, Al, i0, Bh, Bl, j0, ld, (it + 2) * 32);
    }

    if (mode == 0) {
        float* Sb = &g_S[b][0][0];
        const float scale = 0.015625f;       // 4096^-0.5
        #pragma unroll
        for (int mt = 0; mt < 4; mt++) {
            int r0 = i0 + wm + mt * 16 + g;
            #pragma unroll
            for (int nt = 0; nt < 4; nt++) {
                int col = j0 + wn + nt * 8 + t * 2;
                float2 lo = make_float2(acc[mt][nt][0] * scale, acc[mt][nt][1] * scale);
                float2 hi = make_float2(acc[mt][nt][2] * scale, acc[mt][nt][3] * scale);
                *(float2*)&Sb[(size_t)r0 * TOK + col]       = lo;
                *(float2*)&Sb[(size_t)(r0 + 8) * TOK + col] = hi;
            }
        }
    } else {
        #pragma unroll
        for (int mt = 0; mt < 4; mt++) {
            #pragma unroll
            for (int rr = 0; rr < 2; rr++) {
                int i   = i0 + wm + mt * 16 + g + rr * 8;
                int img = b * 16 + (i >> 6);
                int gh  = (i >> 3) & 7;
                int gw  = i & 7;
                #pragma unroll
                for (int nt = 0; nt < 4; nt++) {
                    int d  = j0 + wn + nt * 8 + t * 2;
                    int oc = d >> 6;
                    int pi = (d >> 3) & 7;
                    int pj = d & 7;
                    float2 o = make_float2(acc[mt][nt][rr * 2], acc[mt][nt][rr * 2 + 1]);
                    *(float2*)&g_feat[img][oc][gh * 8 + pi][gw * 8 + pj] = o;
                }
            }
        }
    }
}

// ---------------- kernel: row softmax, writes P hi/lo bf16 ---------------------
__global__ __launch_bounds__(128) void softmax_kernel() {
    const int row = blockIdx.x;            // 0..4095
    const float* p = &g_S[0][0][0] + (size_t)row * TOK;
    __nv_bfloat16* ph = &g_Ph[0][0][0] + (size_t)row * TOK;
    __nv_bfloat16* pl = &g_Pl[0][0][0] + (size_t)row * TOK;
    const int tid = threadIdx.x;
    float v[8];
    float m = -1e30f;
    #pragma unroll
    for (int i = 0; i < 8; i++) { v[i] = p[tid + (i << 7)]; m = fmaxf(m, v[i]); }
    #pragma unroll
    for (int o = 16; o > 0; o >>= 1) m = fmaxf(m, __shfl_xor_sync(0xffffffffu, m, o));
    __shared__ float redm[4], reds[4];
    if ((tid & 31) == 0) redm[tid >> 5] = m;
    __syncthreads();
    m = fmaxf(fmaxf(redm[0], redm[1]), fmaxf(redm[2], redm[3]));
    float sum = 0.f;
    #pragma unroll
    for (int i = 0; i < 8; i++) { v[i] = __expf(v[i] - m); sum += v[i]; }
    #pragma unroll
    for (int o = 16; o > 0; o >>= 1) sum += __shfl_xor_sync(0xffffffffu, sum, o);
    if ((tid & 31) == 0) reds[tid >> 5] = sum;
    __syncthreads();
    sum = reds[0] + reds[1] + reds[2] + reds[3];
    float inv = 1.0f / sum;
    #pragma unroll
    for (int i = 0; i < 8; i++) {
        float pv = v[i] * inv;
        __nv_bfloat16 h = __float2bfloat16(pv);
        ph[tid + (i << 7)] = h;
        pl[tid + (i << 7)] = __float2bfloat16(pv - __bfloat162float(h));
    }
}

// ---------------- launcher ----------------------------------------------------
extern "C" void kernel_launch(void* const* d_in, const int* in_sizes, int n_in,
                              void* d_out, int out_size) {
    (void)in_sizes; (void)n_in; (void)out_size;
    const float* x  = (const float*)d_in[0];
    const float* qw = (const float*)d_in[1];
    const float* qb = (const float*)d_in[2];
    const float* kw = (const float*)d_in[3];
    const float* kb = (const float*)d_in[4];
    const float* vw = (const float*)d_in[5];
    const float* vb = (const float*)d_in[6];
    const float* cw = (const float*)d_in[7];
    const float* cb = (const float*)d_in[8];
    float* out = (float*)d_out;

    const int dsmem = 64 * 10 * 66 * sizeof(float);   // 168,960 B
    const int gsmem = 2 * (int)STAGE_B;               // 81,920 B
    cudaFuncSetAttribute(dwqk_kernel,      cudaFuncAttributeMaxDynamicSharedMemorySize, dsmem);
    cudaFuncSetAttribute(conv_gemm_kernel, cudaFuncAttributeMaxDynamicSharedMemorySize, CG_SMEM);
    cudaFuncSetAttribute(gemm_mma_kernel,  cudaFuncAttributeMaxDynamicSharedMemorySize, gsmem);

    // s0 (default): prep_w -> dwqk -> gemm0 -> softmax -> [join] gemm1 -> conv1
    // s1 (side)   :        \-> conv0 (V conv, independent of attention front-end)
    prep_w_kernel<<<(9 * 64 * 64 + 255) / 256, 256>>>(vw, cw);
    cudaEventRecord(g_ss.e0, 0);
    cudaStreamWaitEvent(g_ss.s1, g_ss.e0, 0);
    conv_gemm_kernel<<<dim3(64, 8), 512, CG_SMEM, g_ss.s1>>>(0, x, vb, nullptr);
    cudaEventRecord(g_ss.e1, g_ss.s1);

    dwqk_kernel<<<dim3(64, 8), 512, dsmem>>>(x, qw, qb, kw, kb);
    gemm_mma_kernel<<<dim3(8, 8, NB), 256, gsmem>>>(0);    // S = QK^T * scale
    softmax_kernel<<<NB * TOK, 128>>>();
    cudaStreamWaitEvent(0, g_ss.e1, 0);
    gemm_mma_kernel<<<dim3(32, 8, NB), 256, gsmem>>>(1);   // feat = fold(P V)
    conv_gemm_kernel<<<dim3(64, 8), 512, CG_SMEM>>>(1, x, cb, out);
}

// round 14
// speedup vs baseline: 1.2673x; 1.2673x over previous
#include <cuda_runtime.h>
#include <cuda_fp16.h>
#include <cstdint>

#define NFC   64
#define HWS   64
#define PSZ   8
#define NB    4
#define NT    16
#define NIMG  64      // NB*NT
#define TOK   1024    // NT * 64 patches
#define DIMD  4096    // NFC * PSZ * PSZ

// ---------------- scratch (static device globals; no allocation) -------------
__device__ __align__(128) __half g_Qh[NB][TOK][DIMD];
__device__ __align__(128) __half g_Ql[NB][TOK][DIMD];
__device__ __align__(128) __half g_Kh[NB][TOK][DIMD];
__device__ __align__(128) __half g_Vth[NB][DIMD][TOK];
__device__ __align__(128) float  g_S [NB][TOK][TOK];
__device__ __align__(128) __half g_Ph[NB][TOK][TOK];
__device__ __align__(128) __half g_Pl[NB][TOK][TOK];
__device__ __align__(128) float g_feat[NIMG][NFC][HWS][HWS];
// conv weights as [tap][oc][ic] fp16 (hi only), pre-swizzled for ldmatrix
__device__ __align__(128) __half g_Wvh[9 * 4096];
__device__ __align__(128) __half g_Wch[9 * 4096];

// ---------------- side stream + events (created once, before main) -----------
struct SideStream {
    cudaStream_t s1;
    cudaEvent_t  e0, e1;
    SideStream() {
        cudaStreamCreateWithFlags(&s1, cudaStreamNonBlocking);
        cudaEventCreateWithFlags(&e0, cudaEventDisableTiming);
        cudaEventCreateWithFlags(&e1, cudaEventDisableTiming);
    }
};
static SideStream g_ss;

// ======================= helpers ==============================================
__device__ __forceinline__ uint32_t smem_u32(const void* p) {
    uint32_t a;
    asm("{ .reg .u64 t; cvta.to.shared.u64 t, %1; cvt.u32.u64 %0, t; }"
        : "=r"(a) : "l"(p));
    return a;
}
__device__ __forceinline__ void cpa16(uint32_t dst, const void* src) {
    asm volatile("cp.async.cg.shared.global [%0], [%1], 16;"
                 :: "r"(dst), "l"(__cvta_generic_to_global(src)));
}
__device__ __forceinline__ void cpa_commit() { asm volatile("cp.async.commit_group;" ::: "memory"); }
__device__ __forceinline__ void cpa_wait1()  { asm volatile("cp.async.wait_group 1;" ::: "memory"); }
__device__ __forceinline__ void cpa_wait0()  { asm volatile("cp.async.wait_group 0;" ::: "memory"); }

__device__ __forceinline__ void mma16816(float* c, const uint32_t* a, const uint32_t* b) {
    asm volatile(
        "mma.sync.aligned.m16n8k16.row.col.f32.f16.f16.f32 "
        "{%0,%1,%2,%3}, {%4,%5,%6,%7}, {%8,%9}, {%0,%1,%2,%3};"
        : "+f"(c[0]), "+f"(c[1]), "+f"(c[2]), "+f"(c[3])
        : "r"(a[0]), "r"(a[1]), "r"(a[2]), "r"(a[3]), "r"(b[0]), "r"(b[1]));
}
__device__ __forceinline__ void ldsm4(uint32_t* r, uint32_t addr) {
    asm volatile("ldmatrix.sync.aligned.m8n8.x4.shared.b16 {%0,%1,%2,%3}, [%4];"
                 : "=r"(r[0]), "=r"(r[1]), "=r"(r[2]), "=r"(r[3]) : "r"(addr));
}

// ---------------- kernel 0: prep conv weights (fp16 hi, swizzled) -------------
__global__ void prep_w_kernel(const float* __restrict__ vw,
                              const float* __restrict__ cw) {
    int idx = blockIdx.x * blockDim.x + threadIdx.x;
    if (idx < 9 * 64 * 64) {
        int t   = idx >> 12;
        int rem = idx & 4095;
        int oc  = rem >> 6;
        int ic  = rem & 63;
        int di  = t * 4096 + oc * 64 + (ic ^ ((oc & 7) << 3));
        g_Wvh[di] = __float2half(vw[oc * 576 + ic * 9 + t]);
        g_Wch[di] = __float2half(cw[oc * 576 + ic * 9 + t]);
    }
}

// ---------------- kernel: depthwise q/k conv -> token-layout fp16 -------------
// Q written hi+lo (GEMM A side), K hi only (GEMM B side).
__global__ __launch_bounds__(512) void dwqk_kernel(
    const float* __restrict__ x,
    const float* __restrict__ qw, const float* __restrict__ qb,
    const float* __restrict__ kw, const float* __restrict__ kb)
{
    extern __shared__ float s[];          // [64][10][66]
    const int img   = blockIdx.x;
    const int ytile = blockIdx.y;
    const int y0    = ytile * 8;
    const int bb    = img >> 4;
    const int tt    = img & 15;
    const int tid   = threadIdx.x;
    const float* xim = x + (size_t)img * NFC * HWS * HWS;

    for (int idx = tid; idx < 64 * 10 * 66; idx += 512) {
        int c  = idx / 660;
        int rr = idx - c * 660;
        int yy = rr / 66;
        int xx = rr - yy * 66;
        int gy = y0 - 1 + yy;
        int gx = xx - 1;
        float v = 0.f;
        if (gy >= 0 && gy < 64 && gx >= 0 && gx < 64)
            v = xim[c * 4096 + gy * 64 + gx];
        s[idx] = v;
    }
    __syncthreads();

    const int c  = tid >> 3;
    const int xb = tid & 7;
    const int x0 = xb * 8;
    const int tok = tt * 64 + ytile * 8 + xb;
    float wq[9], wk[9];
    #pragma unroll
    for (int i = 0; i < 9; i++) { wq[i] = qw[c * 9 + i]; wk[i] = kw[c * 9 + i]; }
    const float bq = qb[c], bk = kb[c];
    const float* sc = s + c * 660;

    #pragma unroll
    for (int y = 0; y < 8; y++) {
        float r0[10], r1[10], r2[10];
        #pragma unroll
        for (int j = 0; j < 10; j++) {
            r0[j] = sc[(y + 0) * 66 + x0 + j];
            r1[j] = sc[(y + 1) * 66 + x0 + j];
            r2[j] = sc[(y + 2) * 66 + x0 + j];
        }
        uint32_t qh4[4], ql4[4], kh4[4];
        #pragma unroll
        for (int pp = 0; pp < 4; pp++) {
            float aq[2], ak[2];
            #pragma unroll
            for (int e = 0; e < 2; e++) {
                int xx = pp * 2 + e;
                float q = bq, k = bk;
                #pragma unroll
                for (int kx = 0; kx < 3; kx++) {
                    q = fmaf(r0[xx + kx], wq[kx], q);
                    q = fmaf(r1[xx + kx], wq[3 + kx], q);
                    q = fmaf(r2[xx + kx], wq[6 + kx], q);
                    k = fmaf(r0[xx + kx], wk[kx], k);
                    k = fmaf(r1[xx + kx], wk[3 + kx], k);
                    k = fmaf(r2[xx + kx], wk[6 + kx], k);
                }
                aq[e] = q; ak[e] = k;
            }
            __half2 h2 = __floats2half2_rn(aq[0], aq[1]);
            qh4[pp] = *(uint32_t*)&h2;
            __half2 l2 = __floats2half2_rn(
                aq[0] - __half2float(__low2half(h2)),
                aq[1] - __half2float(__high2half(h2)));
            ql4[pp] = *(uint32_t*)&l2;
            h2 = __floats2half2_rn(ak[0], ak[1]);
            kh4[pp] = *(uint32_t*)&h2;
        }
        const int d = c * 64 + y * 8;
        *(uint4*)&g_Qh[bb][tok][d] = make_uint4(qh4[0], qh4[1], qh4[2], qh4[3]);
        *(uint4*)&g_Ql[bb][tok][d] = make_uint4(ql4[0], ql4[1], ql4[2], ql4[3]);
        *(uint4*)&g_Kh[bb][tok][d] = make_uint4(kh4[0], kh4[1], kh4[2], kh4[3]);
    }
}

// ---------------- implicit-GEMM conv (tensor cores), both convs ---------------
// mode 0 (V): src = x image; writes Vt fp16 (transposed, +vb)
// mode 1 (C): src = g_feat; writes out = conv + cb + residual x
// X split fp16 hi/lo (A side); weights fp16 hi only (B side). 2 MMA terms.
#define CG_XH    0u
#define CG_XL    84480u
#define CG_W     168960u       // + stage*8192 (hi only)
#define CG_SMEM  185344
#define DB_PITCH 520

__global__ __launch_bounds__(512) void conv_gemm_kernel(
    int mode,
    const float* __restrict__ xin,
    const float* __restrict__ bias,
    float* __restrict__ out)
{
    extern __shared__ char sm[];
    const uint32_t sb = smem_u32(sm);
    const int img   = blockIdx.x;
    const int ytile = blockIdx.y;
    const int y0    = ytile * 8;
    const int tid   = threadIdx.x;
    const int wid   = tid >> 5;
    const int lane  = tid & 31;
    const int lrow  = lane & 15;
    const int lhi   = lane >> 4;
    const int wy    = wid >> 1;          // warp y-row (0..7)
    const int wx0   = (wid & 1) * 32;    // warp x base

    const float* src = (mode == 0) ? (xin + (size_t)img * NFC * HWS * HWS)
                                   : &g_feat[img][0][0][0];
    const __half* Wh = (mode == 0) ? g_Wvh : g_Wch;

    // prefetch weight taps 0,1
    #pragma unroll
    for (int s = 0; s < 2; s++) {
        for (int u = tid; u < 512; u += 512)
            cpa16(sb + CG_W + (uint32_t)s * 8192u + (uint32_t)(u * 16),
                  (const char*)(Wh + s * 4096) + u * 16);
        cpa_commit();
    }

    // load X halo tile -> fp16 hi/lo swizzled [r][c]
    for (int base = 0; base < 42240; base += 512) {
        int idx = base + tid;
        if (idx < 42240) {
            int c  = idx / 660;
            int r  = idx - c * 660;
            int yy = r / 66;
            int xx = r - yy * 66;
            int gy = y0 - 1 + yy, gx = xx - 1;
            float v = 0.f;
            if (gy >= 0 && gy < 64 && gx >= 0 && gx < 64)
                v = src[c * 4096 + gy * 64 + gx];
            __half h = __float2half(v);
            __half l = __float2half(v - __half2float(h));
            uint32_t o = (uint32_t)(r * 128 + 2 * (c ^ ((r & 7) << 3)));
            *(__half*)(sm + CG_XH + o) = h;
            *(__half*)(sm + CG_XL + o) = l;
        }
    }
    __syncthreads();

    // ---- main MMA loop over 9 taps ----
    float acc[2][8][4];
    #pragma unroll
    for (int mt = 0; mt < 2; mt++)
        #pragma unroll
        for (int nt = 0; nt < 8; nt++)
            #pragma unroll
            for (int q = 0; q < 4; q++) acc[mt][nt][q] = 0.f;

    for (int tap = 0; tap < 9; tap++) {
        const int ky = tap / 3;
        const int kx = tap - ky * 3;
        if (tap + 1 < 9) cpa_wait1(); else cpa_wait0();
        __syncthreads();
        const uint32_t wbuf = sb + CG_W + (uint32_t)(tap & 1) * 8192u;
        const int rbase = (wy + ky) * 66 + wx0 + lrow + kx;

        #pragma unroll
        for (int ks = 0; ks < 4; ks++) {
            const uint32_t cofs = (uint32_t)(ks * 32 + lhi * 16);
            uint32_t a[2][4], al[2][4], bh[4][4];
            #pragma unroll
            for (int mt = 0; mt < 2; mt++) {
                int r = rbase + mt * 16;
                ldsm4(a[mt], sb + CG_XH + (uint32_t)(r * 128)
                             + (cofs ^ ((uint32_t)(r & 7) << 4)));
            }
            #pragma unroll
            for (int np = 0; np < 4; np++) {
                int o = np * 16 + lrow;
                ldsm4(bh[np], wbuf + (uint32_t)(o * 128)
                              + (cofs ^ ((uint32_t)(o & 7) << 4)));
            }
            #pragma unroll
            for (int mt = 0; mt < 2; mt++) {
                int r = rbase + mt * 16;
                ldsm4(al[mt], sb + CG_XL + (uint32_t)(r * 128)
                              + (cofs ^ ((uint32_t)(r & 7) << 4)));
            }
            // MMA groups: hh, lh
            #pragma unroll
            for (int mt = 0; mt < 2; mt++)
                #pragma unroll
                for (int nt = 0; nt < 8; nt++) {
                    uint32_t bf[2] = { bh[nt >> 1][nt & 1], bh[nt >> 1][(nt & 1) + 2] };
                    mma16816(acc[mt][nt], a[mt], bf);
                }
            #pragma unroll
            for (int mt = 0; mt < 2; mt++)
                #pragma unroll
                for (int nt = 0; nt < 8; nt++) {
                    uint32_t bf[2] = { bh[nt >> 1][nt & 1], bh[nt >> 1][(nt & 1) + 2] };
                    mma16816(acc[mt][nt], al[mt], bf);
                }
        }
        __syncthreads();
        if (tap + 2 < 9) {
            const int tp = tap + 2;
            const uint32_t dbuf = sb + CG_W + (uint32_t)(tp & 1) * 8192u;
            for (int u = tid; u < 512; u += 512)
                cpa16(dbuf + (uint32_t)(u * 16),
                      (const char*)(Wh + tp * 4096) + u * 16);
            cpa_commit();
        }
    }

    // ---- stage D through smem (X area is dead now), then coalesced writeout ---
    float* Dbuf = (float*)sm;
    const int g  = lane >> 2;
    const int tq = lane & 3;
    #pragma unroll
    for (int mt = 0; mt < 2; mt++)
        #pragma unroll
        for (int rr = 0; rr < 2; rr++) {
            int px = wy * 64 + wx0 + mt * 16 + g + rr * 8;
            #pragma unroll
            for (int nt = 0; nt < 8; nt++) {
                int oc = nt * 8 + tq * 2;
                Dbuf[oc * DB_PITCH + px]       = acc[mt][nt][rr * 2];
                Dbuf[(oc + 1) * DB_PITCH + px] = acc[mt][nt][rr * 2 + 1];
            }
        }
    __syncthreads();

    if (mode == 0) {
        // fused transpose: write Vt[d][tok] fp16
        const int bb = img >> 4, tt = img & 15;
        const int tokbase = tt * 64 + ytile * 8;
        for (int e = tid; e < 32768; e += 512) {
            int d  = e >> 3, xb = e & 7;
            int oc = d >> 6, y = (d >> 3) & 7, xa = d & 7;
            float v = Dbuf[oc * DB_PITCH + y * 64 + xb * 8 + xa] + bias[oc];
            g_Vth[bb][d][tokbase + xb] = __float2half(v);
        }
    } else {
        for (int e = tid; e < 32768; e += 512) {
            int oc = e >> 9, y = (e >> 6) & 7, xx = e & 63;
            int gb = ((img * 64 + oc) * 64 + y0 + y) * 64 + xx;
            out[gb] = Dbuf[oc * DB_PITCH + y * 64 + xx] + bias[oc] + xin[gb];
        }
    }
}

// ---------------- mma.sync GEMM (both attention GEMMs) -------------------------
// CTA tile 128x128, warp tile 64x32 (2x4 warp grid), K-chunk 32.
// A fp16 hi+lo, B fp16 hi. 2 MMA terms (hh, lh).
#define OFF_AH   0u
#define OFF_AL   10240u                 // 128*80
#define OFF_BH   20480u
#define STAGE_B  30720u

__device__ __forceinline__ void load_chunk32(
    uint32_t sb, int tid,
    const __half* Ah, const __half* Al, int i0,
    const __half* Bh, int j0,
    int ld, int k0)
{
    #pragma unroll
    for (int u = tid; u < 1536; u += 256) {
        int part = u >> 9;               // 0:Ah 1:Al 2:Bh
        int idx  = u & 511;              // 128 rows * 4 16B-chunks
        int r = idx >> 2, c = idx & 3;
        const __half* src;
        if      (part == 0) src = Ah + (size_t)(i0 + r) * ld + k0 + c * 8;
        else if (part == 1) src = Al + (size_t)(i0 + r) * ld + k0 + c * 8;
        else                src = Bh + (size_t)(j0 + r) * ld + k0 + c * 8;
        cpa16(sb + (uint32_t)part * 10240u + (uint32_t)(r * 80 + c * 16), src);
    }
    cpa_commit();
}

__global__ __launch_bounds__(256, 2) void gemm_mma_kernel(int mode)
{
    extern __shared__ char dsm[];
    const int tid  = threadIdx.x;
    const int wid  = tid >> 5;
    const int lane = tid & 31;
    const int g    = lane >> 2;          // 0..7
    const int t    = lane & 3;           // 0..3
    const int b    = blockIdx.z;
    const int i0   = blockIdx.y * 128;
    const int j0   = blockIdx.x * 128;
    const int wm   = (wid >> 2) * 64;
    const int wn   = (wid & 3) * 32;
    const int lrow = lane & 15;
    const int lk   = (lane >> 4) << 3;

    const __half *Ah, *Al, *Bh;
    int ld, nch;
    if (mode == 0) {
        Ah = &g_Qh[b][0][0]; Al = &g_Ql[b][0][0];
        Bh = &g_Kh[b][0][0];
        ld = DIMD; nch = DIMD / 32;
    } else {
        Ah = &g_Ph[b][0][0]; Al = &g_Pl[b][0][0];
        Bh = &g_Vth[b][0][0];
        ld = TOK; nch = TOK / 32;
    }

    const uint32_t sbase = smem_u32(dsm);
    float acc[4][4][4];
    #pragma unroll
    for (int mt = 0; mt < 4; mt++)
        #pragma unroll
        for (int nt = 0; nt < 4; nt++)
            #pragma unroll
            for (int q = 0; q < 4; q++) acc[mt][nt][q] = 0.f;

    load_chunk32(sbase,           tid, Ah, Al, i0, Bh, j0, ld, 0);
    load_chunk32(sbase + STAGE_B, tid, Ah, Al, i0, Bh, j0, ld, 32);

    for (int it = 0; it < nch; ++it) {
        const int p = it & 1;
        const uint32_t st = sbase + (uint32_t)p * STAGE_B;
        if (it + 1 < nch) cpa_wait1(); else cpa_wait0();
        __syncthreads();

        #pragma unroll
        for (int ks = 0; ks < 32; ks += 16) {
            uint32_t a[4][4], al[4][4], bh2[2][4];
            const uint32_t cofs = (uint32_t)((ks + lk) * 2);
            #pragma unroll
            for (int mt = 0; mt < 4; mt++)
                ldsm4(a[mt], st + OFF_AH + (uint32_t)((wm + mt * 16 + lrow) * 80) + cofs);
            #pragma unroll
            for (int ntp = 0; ntp < 2; ntp++)
                ldsm4(bh2[ntp], st + OFF_BH + (uint32_t)((wn + ntp * 16 + lrow) * 80) + cofs);
            #pragma unroll
            for (int mt = 0; mt < 4; mt++)
                ldsm4(al[mt], st + OFF_AL + (uint32_t)((wm + mt * 16 + lrow) * 80) + cofs);
            // MMA groups: hh, lh
            #pragma unroll
            for (int mt = 0; mt < 4; mt++)
                #pragma unroll
                for (int nt = 0; nt < 4; nt++) {
                    uint32_t bf[2] = { bh2[nt >> 1][nt & 1], bh2[nt >> 1][(nt & 1) + 2] };
                    mma16816(acc[mt][nt], a[mt], bf);
                }
            #pragma unroll
            for (int mt = 0; mt < 4; mt++)
                #pragma unroll
                for (int nt = 0; nt < 4; nt++) {
                    uint32_t bf[2] = { bh2[nt >> 1][nt & 1], bh2[nt >> 1][(nt & 1) + 2] };
                    mma16816(acc[mt][nt], al[mt], bf);
                }
        }
        __syncthreads();
        if (it + 2 < nch)
            load_chunk32(sbase + (uint32_t)p * STAGE_B, tid,
                         Ah, Al, i0, Bh, j0, ld, (it + 2) * 32);
    }

    if (mode == 0) {
        float* Sb = &g_S[b][0][0];
        const float scale = 0.015625f;       // 4096^-0.5
        #pragma unroll
        for (int mt = 0; mt < 4; mt++) {
            int r0 = i0 + wm + mt * 16 + g;
            #pragma unroll
            for (int nt = 0; nt < 4; nt++) {
                int col = j0 + wn + nt * 8 + t * 2;
                float2 lo = make_float2(acc[mt][nt][0] * scale, acc[mt][nt][1] * scale);
                float2 hi = make_float2(acc[mt][nt][2] * scale, acc[mt][nt][3] * scale);
                *(float2*)&Sb[(size_t)r0 * TOK + col]       = lo;
                *(float2*)&Sb[(size_t)(r0 + 8) * TOK + col] = hi;
            }
        }
    } else {
        #pragma unroll
        for (int mt = 0; mt < 4; mt++) {
            #pragma unroll
            for (int rr = 0; rr < 2; rr++) {
                int i   = i0 + wm + mt * 16 + g + rr * 8;
                int img = b * 16 + (i >> 6);
                int gh  = (i >> 3) & 7;
                int gw  = i & 7;
                #pragma unroll
                for (int nt = 0; nt < 4; nt++) {
                    int d  = j0 + wn + nt * 8 + t * 2;
                    int oc = d >> 6;
                    int pi = (d >> 3) & 7;
                    int pj = d & 7;
                    float2 o = make_float2(acc[mt][nt][rr * 2], acc[mt][nt][rr * 2 + 1]);
                    *(float2*)&g_feat[img][oc][gh * 8 + pi][gw * 8 + pj] = o;
                }
            }
        }
    }
}

// ---------------- kernel: row softmax, writes P hi/lo fp16 ---------------------
__global__ __launch_bounds__(128) void softmax_kernel() {
    const int row = blockIdx.x;            // 0..4095
    const float* p = &g_S[0][0][0] + (size_t)row * TOK;
    __half* ph = &g_Ph[0][0][0] + (size_t)row * TOK;
    __half* pl = &g_Pl[0][0][0] + (size_t)row * TOK;
    const int tid = threadIdx.x;
    float v[8];
    float m = -1e30f;
    #pragma unroll
    for (int i = 0; i < 8; i++) { v[i] = p[tid + (i << 7)]; m = fmaxf(m, v[i]); }
    #pragma unroll
    for (int o = 16; o > 0; o >>= 1) m = fmaxf(m, __shfl_xor_sync(0xffffffffu, m, o));
    __shared__ float redm[4], reds[4];
    if ((tid & 31) == 0) redm[tid >> 5] = m;
    __syncthreads();
    m = fmaxf(fmaxf(redm[0], redm[1]), fmaxf(redm[2], redm[3]));
    float sum = 0.f;
    #pragma unroll
    for (int i = 0; i < 8; i++) { v[i] = __expf(v[i] - m); sum += v[i]; }
    #pragma unroll
    for (int o = 16; o > 0; o >>= 1) sum += __shfl_xor_sync(0xffffffffu, sum, o);
    if ((tid & 31) == 0) reds[tid >> 5] = sum;
    __syncthreads();
    sum = reds[0] + reds[1] + reds[2] + reds[3];
    float inv = 1.0f / sum;
    #pragma unroll
    for (int i = 0; i < 8; i++) {
        float pv = v[i] * inv;
        __half h = __float2half(pv);
        ph[tid + (i << 7)] = h;
        pl[tid + (i << 7)] = __float2half(pv - __half2float(h));
    }
}

// ---------------- launcher ----------------------------------------------------
extern "C" void kernel_launch(void* const* d_in, const int* in_sizes, int n_in,
                              void* d_out, int out_size) {
    (void)in_sizes; (void)n_in; (void)out_size;
    const float* x  = (const float*)d_in[0];
    const float* qw = (const float*)d_in[1];
    const float* qb = (const float*)d_in[2];
    const float* kw = (const float*)d_in[3];
    const float* kb = (const float*)d_in[4];
    const float* vw = (const float*)d_in[5];
    const float* vb = (const float*)d_in[6];
    const float* cw = (const float*)d_in[7];
    const float* cb = (const float*)d_in[8];
    float* out = (float*)d_out;

    const int dsmem = 64 * 10 * 66 * sizeof(float);   // 168,960 B
    const int gsmem = 2 * (int)STAGE_B;               // 61,440 B
    cudaFuncSetAttribute(dwqk_kernel,      cudaFuncAttributeMaxDynamicSharedMemorySize, dsmem);
    cudaFuncSetAttribute(conv_gemm_kernel, cudaFuncAttributeMaxDynamicSharedMemorySize, CG_SMEM);
    cudaFuncSetAttribute(gemm_mma_kernel,  cudaFuncAttributeMaxDynamicSharedMemorySize, gsmem);

    // s0 (default): prep_w -> dwqk -> gemm0 -> softmax -> [join] gemm1 -> conv1
    // s1 (side)   :        \-> conv0 (V conv, independent of attention front-end)
    prep_w_kernel<<<(9 * 64 * 64 + 255) / 256, 256>>>(vw, cw);
    cudaEventRecord(g_ss.e0, 0);
    cudaStreamWaitEvent(g_ss.s1, g_ss.e0, 0);
    conv_gemm_kernel<<<dim3(64, 8), 512, CG_SMEM, g_ss.s1>>>(0, x, vb, nullptr);
    cudaEventRecord(g_ss.e1, g_ss.s1);

    dwqk_kernel<<<dim3(64, 8), 512, dsmem>>>(x, qw, qb, kw, kb);
    gemm_mma_kernel<<<dim3(8, 8, NB), 256, gsmem>>>(0);    // S = QK^T * scale
    softmax_kernel<<<NB * TOK, 128>>>();
    cudaStreamWaitEvent(0, g_ss.e1, 0);
    gemm_mma_kernel<<<dim3(32, 8, NB), 256, gsmem>>>(1);   // feat = fold(P V)
    conv_gemm_kernel<<<dim3(64, 8), 512, CG_SMEM>>>(1, x, cb, out);
}

// round 15
// speedup vs baseline: 1.8693x; 1.4750x over previous
#include <cuda_runtime.h>
#include <cuda_fp16.h>
#include <cstdint>

#define NFC   64
#define HWS   64
#define PSZ   8
#define NB    4
#define NT    16
#define NIMG  64      // NB*NT
#define TOK   1024    // NT * 64 patches
#define DIMD  4096    // NFC * PSZ * PSZ

// ---------------- scratch (static device globals; no allocation) -------------
__device__ __align__(128) __half g_Qh[NB][TOK][DIMD];
__device__ __align__(128) __half g_Kh[NB][TOK][DIMD];
__device__ __align__(128) __half g_Vth[NB][DIMD][TOK];
__device__ __align__(128) float  g_S [NB][TOK][TOK];
__device__ __align__(128) __half g_Ph[NB][TOK][TOK];
__device__ __align__(128) float g_feat[NIMG][NFC][HWS][HWS];
// conv weights as [tap][oc][ic] fp16, pre-swizzled for ldmatrix
__device__ __align__(128) __half g_Wvh[9 * 4096];
__device__ __align__(128) __half g_Wch[9 * 4096];

// ---------------- side stream + events (created once, before main) -----------
struct SideStream {
    cudaStream_t s1;
    cudaEvent_t  e0, e1;
    SideStream() {
        cudaStreamCreateWithFlags(&s1, cudaStreamNonBlocking);
        cudaEventCreateWithFlags(&e0, cudaEventDisableTiming);
        cudaEventCreateWithFlags(&e1, cudaEventDisableTiming);
    }
};
static SideStream g_ss;

// ======================= helpers ==============================================
__device__ __forceinline__ uint32_t smem_u32(const void* p) {
    uint32_t a;
    asm("{ .reg .u64 t; cvta.to.shared.u64 t, %1; cvt.u32.u64 %0, t; }"
        : "=r"(a) : "l"(p));
    return a;
}
__device__ __forceinline__ void cpa16(uint32_t dst, const void* src) {
    asm volatile("cp.async.cg.shared.global [%0], [%1], 16;"
                 :: "r"(dst), "l"(__cvta_generic_to_global(src)));
}
__device__ __forceinline__ void cpa_commit() { asm volatile("cp.async.commit_group;" ::: "memory"); }
__device__ __forceinline__ void cpa_wait1()  { asm volatile("cp.async.wait_group 1;" ::: "memory"); }
__device__ __forceinline__ void cpa_wait0()  { asm volatile("cp.async.wait_group 0;" ::: "memory"); }

__device__ __forceinline__ void mma16816(float* c, const uint32_t* a, const uint32_t* b) {
    asm volatile(
        "mma.sync.aligned.m16n8k16.row.col.f32.f16.f16.f32 "
        "{%0,%1,%2,%3}, {%4,%5,%6,%7}, {%8,%9}, {%0,%1,%2,%3};"
        : "+f"(c[0]), "+f"(c[1]), "+f"(c[2]), "+f"(c[3])
        : "r"(a[0]), "r"(a[1]), "r"(a[2]), "r"(a[3]), "r"(b[0]), "r"(b[1]));
}
__device__ __forceinline__ void ldsm4(uint32_t* r, uint32_t addr) {
    asm volatile("ldmatrix.sync.aligned.m8n8.x4.shared.b16 {%0,%1,%2,%3}, [%4];"
                 : "=r"(r[0]), "=r"(r[1]), "=r"(r[2]), "=r"(r[3]) : "r"(addr));
}

// ---------------- kernel 0: prep conv weights (fp16, swizzled) ----------------
__global__ void prep_w_kernel(const float* __restrict__ vw,
                              const float* __restrict__ cw) {
    int idx = blockIdx.x * blockDim.x + threadIdx.x;
    if (idx < 9 * 64 * 64) {
        int t   = idx >> 12;
        int rem = idx & 4095;
        int oc  = rem >> 6;
        int ic  = rem & 63;
        int di  = t * 4096 + oc * 64 + (ic ^ ((oc & 7) << 3));
        g_Wvh[di] = __float2half(vw[oc * 576 + ic * 9 + t]);
        g_Wch[di] = __float2half(cw[oc * 576 + ic * 9 + t]);
    }
}

// ---------------- kernel: depthwise q/k conv -> token-layout fp16 -------------
__global__ __launch_bounds__(512) void dwqk_kernel(
    const float* __restrict__ x,
    const float* __restrict__ qw, const float* __restrict__ qb,
    const float* __restrict__ kw, const float* __restrict__ kb)
{
    extern __shared__ float s[];          // [64][10][66]
    const int img   = blockIdx.x;
    const int ytile = blockIdx.y;
    const int y0    = ytile * 8;
    const int bb    = img >> 4;
    const int tt    = img & 15;
    const int tid   = threadIdx.x;
    const float* xim = x + (size_t)img * NFC * HWS * HWS;

    for (int idx = tid; idx < 64 * 10 * 66; idx += 512) {
        int c  = idx / 660;
        int rr = idx - c * 660;
        int yy = rr / 66;
        int xx = rr - yy * 66;
        int gy = y0 - 1 + yy;
        int gx = xx - 1;
        float v = 0.f;
        if (gy >= 0 && gy < 64 && gx >= 0 && gx < 64)
            v = xim[c * 4096 + gy * 64 + gx];
        s[idx] = v;
    }
    __syncthreads();

    const int c  = tid >> 3;
    const int xb = tid & 7;
    const int x0 = xb * 8;
    const int tok = tt * 64 + ytile * 8 + xb;
    float wq[9], wk[9];
    #pragma unroll
    for (int i = 0; i < 9; i++) { wq[i] = qw[c * 9 + i]; wk[i] = kw[c * 9 + i]; }
    const float bq = qb[c], bk = kb[c];
    const float* sc = s + c * 660;

    #pragma unroll
    for (int y = 0; y < 8; y++) {
        float r0[10], r1[10], r2[10];
        #pragma unroll
        for (int j = 0; j < 10; j++) {
            r0[j] = sc[(y + 0) * 66 + x0 + j];
            r1[j] = sc[(y + 1) * 66 + x0 + j];
            r2[j] = sc[(y + 2) * 66 + x0 + j];
        }
        uint32_t qh4[4], kh4[4];
        #pragma unroll
        for (int pp = 0; pp < 4; pp++) {
            float aq[2], ak[2];
            #pragma unroll
            for (int e = 0; e < 2; e++) {
                int xx = pp * 2 + e;
                float q = bq, k = bk;
                #pragma unroll
                for (int kx = 0; kx < 3; kx++) {
                    q = fmaf(r0[xx + kx], wq[kx], q);
                    q = fmaf(r1[xx + kx], wq[3 + kx], q);
                    q = fmaf(r2[xx + kx], wq[6 + kx], q);
                    k = fmaf(r0[xx + kx], wk[kx], k);
                    k = fmaf(r1[xx + kx], wk[3 + kx], k);
                    k = fmaf(r2[xx + kx], wk[6 + kx], k);
                }
                aq[e] = q; ak[e] = k;
            }
            __half2 h2 = __floats2half2_rn(aq[0], aq[1]);
            qh4[pp] = *(uint32_t*)&h2;
            h2 = __floats2half2_rn(ak[0], ak[1]);
            kh4[pp] = *(uint32_t*)&h2;
        }
        const int d = c * 64 + y * 8;
        *(uint4*)&g_Qh[bb][tok][d] = make_uint4(qh4[0], qh4[1], qh4[2], qh4[3]);
        *(uint4*)&g_Kh[bb][tok][d] = make_uint4(kh4[0], kh4[1], kh4[2], kh4[3]);
    }
}

// ---------------- implicit-GEMM conv (tensor cores), both convs ---------------
// mode 0 (V): src = x image; writes Vt fp16 (transposed, +vb)
// mode 1 (C): src = g_feat; writes out = conv + cb + residual x
// Pure fp16 single-term. X at [0,84480); weights at 84480 (+ stage*8192).
#define CG_XH    0u
#define CG_W     84480u
#define CG_SMEM  133120        // Dbuf (64*520*4) dominates
#define DB_PITCH 520

__global__ __launch_bounds__(512) void conv_gemm_kernel(
    int mode,
    const float* __restrict__ xin,
    const float* __restrict__ bias,
    float* __restrict__ out)
{
    extern __shared__ char sm[];
    const uint32_t sb = smem_u32(sm);
    const int img   = blockIdx.x;
    const int ytile = blockIdx.y;
    const int y0    = ytile * 8;
    const int tid   = threadIdx.x;
    const int wid   = tid >> 5;
    const int lane  = tid & 31;
    const int lrow  = lane & 15;
    const int lhi   = lane >> 4;
    const int wy    = wid >> 1;          // warp y-row (0..7)
    const int wx0   = (wid & 1) * 32;    // warp x base

    const float* src = (mode == 0) ? (xin + (size_t)img * NFC * HWS * HWS)
                                   : &g_feat[img][0][0][0];
    const __half* Wh = (mode == 0) ? g_Wvh : g_Wch;

    // prefetch weight taps 0,1
    #pragma unroll
    for (int s = 0; s < 2; s++) {
        for (int u = tid; u < 512; u += 512)
            cpa16(sb + CG_W + (uint32_t)s * 8192u + (uint32_t)(u * 16),
                  (const char*)(Wh + s * 4096) + u * 16);
        cpa_commit();
    }

    // load X halo tile -> fp16 swizzled [r][c]
    for (int base = 0; base < 42240; base += 512) {
        int idx = base + tid;
        if (idx < 42240) {
            int c  = idx / 660;
            int r  = idx - c * 660;
            int yy = r / 66;
            int xx = r - yy * 66;
            int gy = y0 - 1 + yy, gx = xx - 1;
            float v = 0.f;
            if (gy >= 0 && gy < 64 && gx >= 0 && gx < 64)
                v = src[c * 4096 + gy * 64 + gx];
            uint32_t o = (uint32_t)(r * 128 + 2 * (c ^ ((r & 7) << 3)));
            *(__half*)(sm + CG_XH + o) = __float2half(v);
        }
    }
    __syncthreads();

    // ---- main MMA loop over 9 taps ----
    float acc[2][8][4];
    #pragma unroll
    for (int mt = 0; mt < 2; mt++)
        #pragma unroll
        for (int nt = 0; nt < 8; nt++)
            #pragma unroll
            for (int q = 0; q < 4; q++) acc[mt][nt][q] = 0.f;

    for (int tap = 0; tap < 9; tap++) {
        const int ky = tap / 3;
        const int kx = tap - ky * 3;
        if (tap + 1 < 9) cpa_wait1(); else cpa_wait0();
        __syncthreads();
        const uint32_t wbuf = sb + CG_W + (uint32_t)(tap & 1) * 8192u;
        const int rbase = (wy + ky) * 66 + wx0 + lrow + kx;

        #pragma unroll
        for (int ks = 0; ks < 4; ks++) {
            const uint32_t cofs = (uint32_t)(ks * 32 + lhi * 16);
            uint32_t a[2][4], bh[4][4];
            #pragma unroll
            for (int mt = 0; mt < 2; mt++) {
                int r = rbase + mt * 16;
                ldsm4(a[mt], sb + CG_XH + (uint32_t)(r * 128)
                             + (cofs ^ ((uint32_t)(r & 7) << 4)));
            }
            #pragma unroll
            for (int np = 0; np < 4; np++) {
                int o = np * 16 + lrow;
                ldsm4(bh[np], wbuf + (uint32_t)(o * 128)
                              + (cofs ^ ((uint32_t)(o & 7) << 4)));
            }
            #pragma unroll
            for (int mt = 0; mt < 2; mt++)
                #pragma unroll
                for (int nt = 0; nt < 8; nt++) {
                    uint32_t bf[2] = { bh[nt >> 1][nt & 1], bh[nt >> 1][(nt & 1) + 2] };
                    mma16816(acc[mt][nt], a[mt], bf);
                }
        }
        __syncthreads();
        if (tap + 2 < 9) {
            const int tp = tap + 2;
            const uint32_t dbuf = sb + CG_W + (uint32_t)(tp & 1) * 8192u;
            for (int u = tid; u < 512; u += 512)
                cpa16(dbuf + (uint32_t)(u * 16),
                      (const char*)(Wh + tp * 4096) + u * 16);
            cpa_commit();
        }
    }

    // ---- stage D through smem (X area is dead now), then coalesced writeout ---
    float* Dbuf = (float*)sm;
    const int g  = lane >> 2;
    const int tq = lane & 3;
    #pragma unroll
    for (int mt = 0; mt < 2; mt++)
        #pragma unroll
        for (int rr = 0; rr < 2; rr++) {
            int px = wy * 64 + wx0 + mt * 16 + g + rr * 8;
            #pragma unroll
            for (int nt = 0; nt < 8; nt++) {
                int oc = nt * 8 + tq * 2;
                Dbuf[oc * DB_PITCH + px]       = acc[mt][nt][rr * 2];
                Dbuf[(oc + 1) * DB_PITCH + px] = acc[mt][nt][rr * 2 + 1];
            }
        }
    __syncthreads();

    if (mode == 0) {
        // fused transpose: write Vt[d][tok] fp16
        const int bb = img >> 4, tt = img & 15;
        const int tokbase = tt * 64 + ytile * 8;
        for (int e = tid; e < 32768; e += 512) {
            int d  = e >> 3, xb = e & 7;
            int oc = d >> 6, y = (d >> 3) & 7, xa = d & 7;
            float v = Dbuf[oc * DB_PITCH + y * 64 + xb * 8 + xa] + bias[oc];
            g_Vth[bb][d][tokbase + xb] = __float2half(v);
        }
    } else {
        for (int e = tid; e < 32768; e += 512) {
            int oc = e >> 9, y = (e >> 6) & 7, xx = e & 63;
            int gb = ((img * 64 + oc) * 64 + y0 + y) * 64 + xx;
            out[gb] = Dbuf[oc * DB_PITCH + y * 64 + xx] + bias[oc] + xin[gb];
        }
    }
}

// ---------------- mma.sync GEMM (both attention GEMMs) -------------------------
// CTA tile 128x128, warp tile 64x32 (2x4 warp grid), K-chunk 32. Pure fp16.
#define OFF_A    0u
#define OFF_B    10240u                 // 128*80
#define STAGE_B  20480u

__device__ __forceinline__ void load_chunk32(
    uint32_t sb, int tid,
    const __half* A, int i0,
    const __half* Bm, int j0,
    int ld, int k0)
{
    #pragma unroll
    for (int u = tid; u < 1024; u += 256) {
        int part = u >> 9;               // 0:A 1:B
        int idx  = u & 511;              // 128 rows * 4 16B-chunks
        int r = idx >> 2, c = idx & 3;
        const __half* src = (part ? Bm + (size_t)(j0 + r) * ld
                                  : A  + (size_t)(i0 + r) * ld) + k0 + c * 8;
        cpa16(sb + (uint32_t)part * 10240u + (uint32_t)(r * 80 + c * 16), src);
    }
    cpa_commit();
}

__global__ __launch_bounds__(256, 2) void gemm_mma_kernel(int mode)
{
    extern __shared__ char dsm[];
    const int tid  = threadIdx.x;
    const int wid  = tid >> 5;
    const int lane = tid & 31;
    const int g    = lane >> 2;          // 0..7
    const int t    = lane & 3;           // 0..3
    const int b    = blockIdx.z;
    const int i0   = blockIdx.y * 128;
    const int j0   = blockIdx.x * 128;
    const int wm   = (wid >> 2) * 64;
    const int wn   = (wid & 3) * 32;
    const int lrow = lane & 15;
    const int lk   = (lane >> 4) << 3;

    const __half *A, *Bm;
    int ld, nch;
    if (mode == 0) {
        A = &g_Qh[b][0][0]; Bm = &g_Kh[b][0][0];
        ld = DIMD; nch = DIMD / 32;
    } else {
        A = &g_Ph[b][0][0]; Bm = &g_Vth[b][0][0];
        ld = TOK; nch = TOK / 32;
    }

    const uint32_t sbase = smem_u32(dsm);
    float acc[4][4][4];
    #pragma unroll
    for (int mt = 0; mt < 4; mt++)
        #pragma unroll
        for (int nt = 0; nt < 4; nt++)
            #pragma unroll
            for (int q = 0; q < 4; q++) acc[mt][nt][q] = 0.f;

    load_chunk32(sbase,           tid, A, i0, Bm, j0, ld, 0);
    load_chunk32(sbase + STAGE_B, tid, A, i0, Bm, j0, ld, 32);

    for (int it = 0; it < nch; ++it) {
        const int p = it & 1;
        const uint32_t st = sbase + (uint32_t)p * STAGE_B;
        if (it + 1 < nch) cpa_wait1(); else cpa_wait0();
        __syncthreads();

        #pragma unroll
        for (int ks = 0; ks < 32; ks += 16) {
            uint32_t a[4][4], bh2[2][4];
            const uint32_t cofs = (uint32_t)((ks + lk) * 2);
            #pragma unroll
            for (int mt = 0; mt < 4; mt++)
                ldsm4(a[mt], st + OFF_A + (uint32_t)((wm + mt * 16 + lrow) * 80) + cofs);
            #pragma unroll
            for (int ntp = 0; ntp < 2; ntp++)
                ldsm4(bh2[ntp], st + OFF_B + (uint32_t)((wn + ntp * 16 + lrow) * 80) + cofs);
            #pragma unroll
            for (int mt = 0; mt < 4; mt++)
                #pragma unroll
                for (int nt = 0; nt < 4; nt++) {
                    uint32_t bf[2] = { bh2[nt >> 1][nt & 1], bh2[nt >> 1][(nt & 1) + 2] };
                    mma16816(acc[mt][nt], a[mt], bf);
                }
        }
        __syncthreads();
        if (it + 2 < nch)
            load_chunk32(sbase + (uint32_t)p * STAGE_B, tid,
                         A, i0, Bm, j0, ld, (it + 2) * 32);
    }

    if (mode == 0) {
        float* Sb = &g_S[b][0][0];
        const float scale = 0.015625f;       // 4096^-0.5
        #pragma unroll
        for (int mt = 0; mt < 4; mt++) {
            int r0 = i0 + wm + mt * 16 + g;
            #pragma unroll
            for (int nt = 0; nt < 4; nt++) {
                int col = j0 + wn + nt * 8 + t * 2;
                float2 lo = make_float2(acc[mt][nt][0] * scale, acc[mt][nt][1] * scale);
                float2 hi = make_float2(acc[mt][nt][2] * scale, acc[mt][nt][3] * scale);
                *(float2*)&Sb[(size_t)r0 * TOK + col]       = lo;
                *(float2*)&Sb[(size_t)(r0 + 8) * TOK + col] = hi;
            }
        }
    } else {
        #pragma unroll
        for (int mt = 0; mt < 4; mt++) {
            #pragma unroll
            for (int rr = 0; rr < 2; rr++) {
                int i   = i0 + wm + mt * 16 + g + rr * 8;
                int img = b * 16 + (i >> 6);
                int gh  = (i >> 3) & 7;
                int gw  = i & 7;
                #pragma unroll
                for (int nt = 0; nt < 4; nt++) {
                    int d  = j0 + wn + nt * 8 + t * 2;
                    int oc = d >> 6;
                    int pi = (d >> 3) & 7;
                    int pj = d & 7;
                    float2 o = make_float2(acc[mt][nt][rr * 2], acc[mt][nt][rr * 2 + 1]);
                    *(float2*)&g_feat[img][oc][gh * 8 + pi][gw * 8 + pj] = o;
                }
            }
        }
    }
}

// ---------------- kernel: row softmax, writes P fp16 ---------------------------
__global__ __launch_bounds__(128) void softmax_kernel() {
    const int row = blockIdx.x;            // 0..4095
    const float* p = &g_S[0][0][0] + (size_t)row * TOK;
    __half* ph = &g_Ph[0][0][0] + (size_t)row * TOK;
    const int tid = threadIdx.x;
    float v[8];
    float m = -1e30f;
    #pragma unroll
    for (int i = 0; i < 8; i++) { v[i] = p[tid + (i << 7)]; m = fmaxf(m, v[i]); }
    #pragma unroll
    for (int o = 16; o > 0; o >>= 1) m = fmaxf(m, __shfl_xor_sync(0xffffffffu, m, o));
    __shared__ float redm[4], reds[4];
    if ((tid & 31) == 0) redm[tid >> 5] = m;
    __syncthreads();
    m = fmaxf(fmaxf(redm[0], redm[1]), fmaxf(redm[2], redm[3]));
    float sum = 0.f;
    #pragma unroll
    for (int i = 0; i < 8; i++) { v[i] = __expf(v[i] - m); sum += v[i]; }
    #pragma unroll
    for (int o = 16; o > 0; o >>= 1) sum += __shfl_xor_sync(0xffffffffu, sum, o);
    if ((tid & 31) == 0) reds[tid >> 5] = sum;
    __syncthreads();
    sum = reds[0] + reds[1] + reds[2] + reds[3];
    float inv = 1.0f / sum;
    #pragma unroll
    for (int i = 0; i < 8; i++)
        ph[tid + (i << 7)] = __float2half(v[i] * inv);
}

// ---------------- launcher ----------------------------------------------------
extern "C" void kernel_launch(void* const* d_in, const int* in_sizes, int n_in,
                              void* d_out, int out_size) {
    (void)in_sizes; (void)n_in; (void)out_size;
    const float* x  = (const float*)d_in[0];
    const float* qw = (const float*)d_in[1];
    const float* qb = (const float*)d_in[2];
    const float* kw = (const float*)d_in[3];
    const float* kb = (const float*)d_in[4];
    const float* vw = (const float*)d_in[5];
    const float* vb = (const float*)d_in[6];
    const float* cw = (const float*)d_in[7];
    const float* cb = (const float*)d_in[8];
    float* out = (float*)d_out;

    const int dsmem = 64 * 10 * 66 * sizeof(float);   // 168,960 B
    const int gsmem = 2 * (int)STAGE_B;               // 40,960 B
    cudaFuncSetAttribute(dwqk_kernel,      cudaFuncAttributeMaxDynamicSharedMemorySize, dsmem);
    cudaFuncSetAttribute(conv_gemm_kernel, cudaFuncAttributeMaxDynamicSharedMemorySize, CG_SMEM);
    cudaFuncSetAttribute(gemm_mma_kernel,  cudaFuncAttributeMaxDynamicSharedMemorySize, gsmem);

    // s0 (default): prep_w -> dwqk -> gemm0 -> softmax -> [join] gemm1 -> conv1
    // s1 (side)   :        \-> conv0 (V conv, independent of attention front-end)
    prep_w_kernel<<<(9 * 64 * 64 + 255) / 256, 256>>>(vw, cw);
    cudaEventRecord(g_ss.e0, 0);
    cudaStreamWaitEvent(g_ss.s1, g_ss.e0, 0);
    conv_gemm_kernel<<<dim3(64, 8), 512, CG_SMEM, g_ss.s1>>>(0, x, vb, nullptr);
    cudaEventRecord(g_ss.e1, g_ss.s1);

    dwqk_kernel<<<dim3(64, 8), 512, dsmem>>>(x, qw, qb, kw, kb);
    gemm_mma_kernel<<<dim3(8, 8, NB), 256, gsmem>>>(0);    // S = QK^T * scale
    softmax_kernel<<<NB * TOK, 128>>>();
    cudaStreamWaitEvent(0, g_ss.e1, 0);
    gemm_mma_kernel<<<dim3(32, 8, NB), 256, gsmem>>>(1);   // feat = fold(P V)
    conv_gemm_kernel<<<dim3(64, 8), 512, CG_SMEM>>>(1, x, cb, out);
}

// round 16
// speedup vs baseline: 1.8819x; 1.0067x over previous
#include <cuda_runtime.h>
#include <cuda_fp16.h>
#include <cstdint>

#define NFC   64
#define HWS   64
#define PSZ   8
#define NB    4
#define NT    16
#define NIMG  64      // NB*NT
#define TOK   1024    // NT * 64 patches
#define DIMD  4096    // NFC * PSZ * PSZ

// ---------------- scratch (static device globals; no allocation) -------------
__device__ __align__(128) __half g_Qh[NB][TOK][DIMD];
__device__ __align__(128) __half g_Kh[NB][TOK][DIMD];
__device__ __align__(128) __half g_Vth[NB][DIMD][TOK];
__device__ __align__(128) float  g_S [NB][TOK][TOK];
__device__ __align__(128) __half g_Ph[NB][TOK][TOK];
__device__ __align__(128) float g_feat[NIMG][NFC][HWS][HWS];
// conv weights as [tap][oc][ic] fp16, pre-swizzled for ldmatrix
__device__ __align__(128) __half g_Wvh[9 * 4096];
__device__ __align__(128) __half g_Wch[9 * 4096];

// ---------------- side stream + events (created once, before main) -----------
struct SideStream {
    cudaStream_t s1;
    cudaEvent_t  e0, e1;
    SideStream() {
        cudaStreamCreateWithFlags(&s1, cudaStreamNonBlocking);
        cudaEventCreateWithFlags(&e0, cudaEventDisableTiming);
        cudaEventCreateWithFlags(&e1, cudaEventDisableTiming);
    }
};
static SideStream g_ss;

// ======================= helpers ==============================================
__device__ __forceinline__ uint32_t smem_u32(const void* p) {
    uint32_t a;
    asm("{ .reg .u64 t; cvta.to.shared.u64 t, %1; cvt.u32.u64 %0, t; }"
        : "=r"(a) : "l"(p));
    return a;
}
__device__ __forceinline__ void cpa16(uint32_t dst, const void* src) {
    asm volatile("cp.async.cg.shared.global [%0], [%1], 16;"
                 :: "r"(dst), "l"(__cvta_generic_to_global(src)));
}
__device__ __forceinline__ void cpa_commit() { asm volatile("cp.async.commit_group;" ::: "memory"); }
__device__ __forceinline__ void cpa_wait2()  { asm volatile("cp.async.wait_group 2;" ::: "memory"); }
__device__ __forceinline__ void cpa_wait1()  { asm volatile("cp.async.wait_group 1;" ::: "memory"); }
__device__ __forceinline__ void cpa_wait0()  { asm volatile("cp.async.wait_group 0;" ::: "memory"); }

__device__ __forceinline__ void mma16816(float* c, const uint32_t* a, const uint32_t* b) {
    asm volatile(
        "mma.sync.aligned.m16n8k16.row.col.f32.f16.f16.f32 "
        "{%0,%1,%2,%3}, {%4,%5,%6,%7}, {%8,%9}, {%0,%1,%2,%3};"
        : "+f"(c[0]), "+f"(c[1]), "+f"(c[2]), "+f"(c[3])
        : "r"(a[0]), "r"(a[1]), "r"(a[2]), "r"(a[3]), "r"(b[0]), "r"(b[1]));
}
__device__ __forceinline__ void ldsm4(uint32_t* r, uint32_t addr) {
    asm volatile("ldmatrix.sync.aligned.m8n8.x4.shared.b16 {%0,%1,%2,%3}, [%4];"
                 : "=r"(r[0]), "=r"(r[1]), "=r"(r[2]), "=r"(r[3]) : "r"(addr));
}

// ---------------- kernel 0: prep conv weights (fp16, swizzled) ----------------
__global__ void prep_w_kernel(const float* __restrict__ vw,
                              const float* __restrict__ cw) {
    int idx = blockIdx.x * blockDim.x + threadIdx.x;
    if (idx < 9 * 64 * 64) {
        int t   = idx >> 12;
        int rem = idx & 4095;
        int oc  = rem >> 6;
        int ic  = rem & 63;
        int di  = t * 4096 + oc * 64 + (ic ^ ((oc & 7) << 3));
        g_Wvh[di] = __float2half(vw[oc * 576 + ic * 9 + t]);
        g_Wch[di] = __float2half(cw[oc * 576 + ic * 9 + t]);
    }
}

// ---------------- kernel: depthwise q/k conv -> token-layout fp16 -------------
__global__ __launch_bounds__(512) void dwqk_kernel(
    const float* __restrict__ x,
    const float* __restrict__ qw, const float* __restrict__ qb,
    const float* __restrict__ kw, const float* __restrict__ kb)
{
    extern __shared__ float s[];          // [64][10][66]
    const int img   = blockIdx.x;
    const int ytile = blockIdx.y;
    const int y0    = ytile * 8;
    const int bb    = img >> 4;
    const int tt    = img & 15;
    const int tid   = threadIdx.x;
    const float* xim = x + (size_t)img * NFC * HWS * HWS;

    for (int idx = tid; idx < 64 * 10 * 66; idx += 512) {
        int c  = idx / 660;
        int rr = idx - c * 660;
        int yy = rr / 66;
        int xx = rr - yy * 66;
        int gy = y0 - 1 + yy;
        int gx = xx - 1;
        float v = 0.f;
        if (gy >= 0 && gy < 64 && gx >= 0 && gx < 64)
            v = xim[c * 4096 + gy * 64 + gx];
        s[idx] = v;
    }
    __syncthreads();

    const int c  = tid >> 3;
    const int xb = tid & 7;
    const int x0 = xb * 8;
    const int tok = tt * 64 + ytile * 8 + xb;
    float wq[9], wk[9];
    #pragma unroll
    for (int i = 0; i < 9; i++) { wq[i] = qw[c * 9 + i]; wk[i] = kw[c * 9 + i]; }
    const float bq = qb[c], bk = kb[c];
    const float* sc = s + c * 660;

    #pragma unroll
    for (int y = 0; y < 8; y++) {
        float r0[10], r1[10], r2[10];
        #pragma unroll
        for (int j = 0; j < 10; j++) {
            r0[j] = sc[(y + 0) * 66 + x0 + j];
            r1[j] = sc[(y + 1) * 66 + x0 + j];
            r2[j] = sc[(y + 2) * 66 + x0 + j];
        }
        uint32_t qh4[4], kh4[4];
        #pragma unroll
        for (int pp = 0; pp < 4; pp++) {
            float aq[2], ak[2];
            #pragma unroll
            for (int e = 0; e < 2; e++) {
                int xx = pp * 2 + e;
                float q = bq, k = bk;
                #pragma unroll
                for (int kx = 0; kx < 3; kx++) {
                    q = fmaf(r0[xx + kx], wq[kx], q);
                    q = fmaf(r1[xx + kx], wq[3 + kx], q);
                    q = fmaf(r2[xx + kx], wq[6 + kx], q);
                    k = fmaf(r0[xx + kx], wk[kx], k);
                    k = fmaf(r1[xx + kx], wk[3 + kx], k);
                    k = fmaf(r2[xx + kx], wk[6 + kx], k);
                }
                aq[e] = q; ak[e] = k;
            }
            __half2 h2 = __floats2half2_rn(aq[0], aq[1]);
            qh4[pp] = *(uint32_t*)&h2;
            h2 = __floats2half2_rn(ak[0], ak[1]);
            kh4[pp] = *(uint32_t*)&h2;
        }
        const int d = c * 64 + y * 8;
        *(uint4*)&g_Qh[bb][tok][d] = make_uint4(qh4[0], qh4[1], qh4[2], qh4[3]);
        *(uint4*)&g_Kh[bb][tok][d] = make_uint4(kh4[0], kh4[1], kh4[2], kh4[3]);
    }
}

// ---------------- implicit-GEMM conv (tensor cores), both convs ---------------
// mode 0 (V): src = x image; writes Vt fp16 (transposed, +vb)
// mode 1 (C): src = g_feat; writes out = conv + cb + residual x
// All 9 weight taps preloaded -> zero barriers in the MMA loop.
#define CG_XH    0u
#define CG_W     84480u        // 9 taps * 8192 B
#define CG_SMEM  158208
#define DB_PITCH 520

__global__ __launch_bounds__(512) void conv_gemm_kernel(
    int mode,
    const float* __restrict__ xin,
    const float* __restrict__ bias,
    float* __restrict__ out)
{
    extern __shared__ char sm[];
    const uint32_t sb = smem_u32(sm);
    const int img   = blockIdx.x;
    const int ytile = blockIdx.y;
    const int y0    = ytile * 8;
    const int tid   = threadIdx.x;
    const int wid   = tid >> 5;
    const int lane  = tid & 31;
    const int lrow  = lane & 15;
    const int lhi   = lane >> 4;
    const int wy    = wid >> 1;          // warp y-row (0..7)
    const int wx0   = (wid & 1) * 32;    // warp x base

    const float* src = (mode == 0) ? (xin + (size_t)img * NFC * HWS * HWS)
                                   : &g_feat[img][0][0][0];
    const __half* Wh = (mode == 0) ? g_Wvh : g_Wch;

    // prefetch ALL 9 weight taps (one group)
    for (int u = tid; u < 9 * 512; u += 512)
        cpa16(sb + CG_W + (uint32_t)(u * 16), (const char*)Wh + u * 16);
    cpa_commit();

    // load X halo tile -> fp16 swizzled [r][c]
    for (int base = 0; base < 42240; base += 512) {
        int idx = base + tid;
        if (idx < 42240) {
            int c  = idx / 660;
            int r  = idx - c * 660;
            int yy = r / 66;
            int xx = r - yy * 66;
            int gy = y0 - 1 + yy, gx = xx - 1;
            float v = 0.f;
            if (gy >= 0 && gy < 64 && gx >= 0 && gx < 64)
                v = src[c * 4096 + gy * 64 + gx];
            uint32_t o = (uint32_t)(r * 128 + 2 * (c ^ ((r & 7) << 3)));
            *(__half*)(sm + CG_XH + o) = __float2half(v);
        }
    }
    cpa_wait0();
    __syncthreads();

    // ---- main MMA loop: 9 taps x 4 k16 steps, no barriers ----
    float acc[2][8][4];
    #pragma unroll
    for (int mt = 0; mt < 2; mt++)
        #pragma unroll
        for (int nt = 0; nt < 8; nt++)
            #pragma unroll
            for (int q = 0; q < 4; q++) acc[mt][nt][q] = 0.f;

    for (int tap = 0; tap < 9; tap++) {
        const int ky = tap / 3;
        const int kx = tap - ky * 3;
        const uint32_t wbuf = sb + CG_W + (uint32_t)tap * 8192u;
        const int rbase = (wy + ky) * 66 + wx0 + lrow + kx;

        #pragma unroll
        for (int ks = 0; ks < 4; ks++) {
            const uint32_t cofs = (uint32_t)(ks * 32 + lhi * 16);
            uint32_t a[2][4], bh[4][4];
            #pragma unroll
            for (int mt = 0; mt < 2; mt++) {
                int r = rbase + mt * 16;
                ldsm4(a[mt], sb + CG_XH + (uint32_t)(r * 128)
                             + (cofs ^ ((uint32_t)(r & 7) << 4)));
            }
            #pragma unroll
            for (int np = 0; np < 4; np++) {
                int o = np * 16 + lrow;
                ldsm4(bh[np], wbuf + (uint32_t)(o * 128)
                              + (cofs ^ ((uint32_t)(o & 7) << 4)));
            }
            #pragma unroll
            for (int mt = 0; mt < 2; mt++)
                #pragma unroll
                for (int nt = 0; nt < 8; nt++) {
                    uint32_t bf[2] = { bh[nt >> 1][nt & 1], bh[nt >> 1][(nt & 1) + 2] };
                    mma16816(acc[mt][nt], a[mt], bf);
                }
        }
    }
    __syncthreads();   // all warps done reading X before Dbuf overwrite

    // ---- stage D through smem, then coalesced writeout ----
    float* Dbuf = (float*)sm;
    const int g  = lane >> 2;
    const int tq = lane & 3;
    #pragma unroll
    for (int mt = 0; mt < 2; mt++)
        #pragma unroll
        for (int rr = 0; rr < 2; rr++) {
            int px = wy * 64 + wx0 + mt * 16 + g + rr * 8;
            #pragma unroll
            for (int nt = 0; nt < 8; nt++) {
                int oc = nt * 8 + tq * 2;
                Dbuf[oc * DB_PITCH + px]       = acc[mt][nt][rr * 2];
                Dbuf[(oc + 1) * DB_PITCH + px] = acc[mt][nt][rr * 2 + 1];
            }
        }
    __syncthreads();

    if (mode == 0) {
        // fused transpose: write Vt[d][tok] fp16
        const int bb = img >> 4, tt = img & 15;
        const int tokbase = tt * 64 + ytile * 8;
        for (int e = tid; e < 32768; e += 512) {
            int d  = e >> 3, xb = e & 7;
            int oc = d >> 6, y = (d >> 3) & 7, xa = d & 7;
            float v = Dbuf[oc * DB_PITCH + y * 64 + xb * 8 + xa] + bias[oc];
            g_Vth[bb][d][tokbase + xb] = __float2half(v);
        }
    } else {
        for (int e = tid; e < 32768; e += 512) {
            int oc = e >> 9, y = (e >> 6) & 7, xx = e & 63;
            int gb = ((img * 64 + oc) * 64 + y0 + y) * 64 + xx;
            out[gb] = Dbuf[oc * DB_PITCH + y * 64 + xx] + bias[oc] + xin[gb];
        }
    }
}

// ---------------- mma.sync GEMM (both attention GEMMs) -------------------------
// CTA tile 128x128, warp tile 64x32 (2x4 warp grid), K-chunk 32.
// 4-stage cp.async pipeline, ONE barrier per chunk.
#define OFF_A    0u
#define OFF_B    10240u                 // 128*80
#define STAGE_B  20480u

__device__ __forceinline__ void load_chunk32(
    uint32_t sb, int tid,
    const __half* A, int i0,
    const __half* Bm, int j0,
    int ld, int k0)
{
    #pragma unroll
    for (int u = tid; u < 1024; u += 256) {
        int part = u >> 9;               // 0:A 1:B
        int idx  = u & 511;              // 128 rows * 4 16B-chunks
        int r = idx >> 2, c = idx & 3;
        const __half* src = (part ? Bm + (size_t)(j0 + r) * ld
                                  : A  + (size_t)(i0 + r) * ld) + k0 + c * 8;
        cpa16(sb + (uint32_t)part * 10240u + (uint32_t)(r * 80 + c * 16), src);
    }
    cpa_commit();
}

__global__ __launch_bounds__(256, 2) void gemm_mma_kernel(int mode)
{
    extern __shared__ char dsm[];
    const int tid  = threadIdx.x;
    const int wid  = tid >> 5;
    const int lane = tid & 31;
    const int g    = lane >> 2;          // 0..7
    const int t    = lane & 3;           // 0..3
    const int b    = blockIdx.z;
    const int i0   = blockIdx.y * 128;
    const int j0   = blockIdx.x * 128;
    const int wm   = (wid >> 2) * 64;
    const int wn   = (wid & 3) * 32;
    const int lrow = lane & 15;
    const int lk   = (lane >> 4) << 3;

    const __half *A, *Bm;
    int ld, nch;
    if (mode == 0) {
        A = &g_Qh[b][0][0]; Bm = &g_Kh[b][0][0];
        ld = DIMD; nch = DIMD / 32;
    } else {
        A = &g_Ph[b][0][0]; Bm = &g_Vth[b][0][0];
        ld = TOK; nch = TOK / 32;
    }

    const uint32_t sbase = smem_u32(dsm);
    float acc[4][4][4];
    #pragma unroll
    for (int mt = 0; mt < 4; mt++)
        #pragma unroll
        for (int nt = 0; nt < 4; nt++)
            #pragma unroll
            for (int q = 0; q < 4; q++) acc[mt][nt][q] = 0.f;

    // prologue: 3 chunks in flight
    load_chunk32(sbase,               tid, A, i0, Bm, j0, ld, 0);
    load_chunk32(sbase +     STAGE_B, tid, A, i0, Bm, j0, ld, 32);
    load_chunk32(sbase + 2 * STAGE_B, tid, A, i0, Bm, j0, ld, 64);

    for (int it = 0; it < nch; ++it) {
        const uint32_t st = sbase + (uint32_t)(it & 3) * STAGE_B;
        if      (it + 2 < nch) cpa_wait2();
        else if (it + 1 < nch) cpa_wait1();
        else                   cpa_wait0();
        __syncthreads();
        // prefetch chunk it+3 into the stage freed at iteration it-1
        if (it + 3 < nch)
            load_chunk32(sbase + (uint32_t)((it + 3) & 3) * STAGE_B,
                         tid, A, i0, Bm, j0, ld, (it + 3) * 32);

        #pragma unroll
        for (int ks = 0; ks < 32; ks += 16) {
            uint32_t a[4][4], bh2[2][4];
            const uint32_t cofs = (uint32_t)((ks + lk) * 2);
            #pragma unroll
            for (int mt = 0; mt < 4; mt++)
                ldsm4(a[mt], st + OFF_A + (uint32_t)((wm + mt * 16 + lrow) * 80) + cofs);
            #pragma unroll
            for (int ntp = 0; ntp < 2; ntp++)
                ldsm4(bh2[ntp], st + OFF_B + (uint32_t)((wn + ntp * 16 + lrow) * 80) + cofs);
            #pragma unroll
            for (int mt = 0; mt < 4; mt++)
                #pragma unroll
                for (int nt = 0; nt < 4; nt++) {
                    uint32_t bf[2] = { bh2[nt >> 1][nt & 1], bh2[nt >> 1][(nt & 1) + 2] };
                    mma16816(acc[mt][nt], a[mt], bf);
                }
        }
    }

    if (mode == 0) {
        float* Sb = &g_S[b][0][0];
        const float scale = 0.015625f;       // 4096^-0.5
        #pragma unroll
        for (int mt = 0; mt < 4; mt++) {
            int r0 = i0 + wm + mt * 16 + g;
            #pragma unroll
            for (int nt = 0; nt < 4; nt++) {
                int col = j0 + wn + nt * 8 + t * 2;
                float2 lo = make_float2(acc[mt][nt][0] * scale, acc[mt][nt][1] * scale);
                float2 hi = make_float2(acc[mt][nt][2] * scale, acc[mt][nt][3] * scale);
                *(float2*)&Sb[(size_t)r0 * TOK + col]       = lo;
                *(float2*)&Sb[(size_t)(r0 + 8) * TOK + col] = hi;
            }
        }
    } else {
        #pragma unroll
        for (int mt = 0; mt < 4; mt++) {
            #pragma unroll
            for (int rr = 0; rr < 2; rr++) {
                int i   = i0 + wm + mt * 16 + g + rr * 8;
                int img = b * 16 + (i >> 6);
                int gh  = (i >> 3) & 7;
                int gw  = i & 7;
                #pragma unroll
                for (int nt = 0; nt < 4; nt++) {
                    int d  = j0 + wn + nt * 8 + t * 2;
                    int oc = d >> 6;
                    int pi = (d >> 3) & 7;
                    int pj = d & 7;
                    float2 o = make_float2(acc[mt][nt][rr * 2], acc[mt][nt][rr * 2 + 1]);
                    *(float2*)&g_feat[img][oc][gh * 8 + pi][gw * 8 + pj] = o;
                }
            }
        }
    }
}

// ---------------- kernel: row softmax, writes P fp16 ---------------------------
__global__ __launch_bounds__(128) void softmax_kernel() {
    const int row = blockIdx.x;            // 0..4095
    const float* p = &g_S[0][0][0] + (size_t)row * TOK;
    __half* ph = &g_Ph[0][0][0] + (size_t)row * TOK;
    const int tid = threadIdx.x;
    float v[8];
    float m = -1e30f;
    #pragma unroll
    for (int i = 0; i < 8; i++) { v[i] = p[tid + (i << 7)]; m = fmaxf(m, v[i]); }
    #pragma unroll
    for (int o = 16; o > 0; o >>= 1) m = fmaxf(m, __shfl_xor_sync(0xffffffffu, m, o));
    __shared__ float redm[4], reds[4];
    if ((tid & 31) == 0) redm[tid >> 5] = m;
    __syncthreads();
    m = fmaxf(fmaxf(redm[0], redm[1]), fmaxf(redm[2], redm[3]));
    float sum = 0.f;
    #pragma unroll
    for (int i = 0; i < 8; i++) { v[i] = __expf(v[i] - m); sum += v[i]; }
    #pragma unroll
    for (int o = 16; o > 0; o >>= 1) sum += __shfl_xor_sync(0xffffffffu, sum, o);
    if ((tid & 31) == 0) reds[tid >> 5] = sum;
    __syncthreads();
    sum = reds[0] + reds[1] + reds[2] + reds[3];
    float inv = 1.0f / sum;
    #pragma unroll
    for (int i = 0; i < 8; i++)
        ph[tid + (i << 7)] = __float2half(v[i] * inv);
}

// ---------------- launcher ----------------------------------------------------
extern "C" void kernel_launch(void* const* d_in, const int* in_sizes, int n_in,
                              void* d_out, int out_size) {
    (void)in_sizes; (void)n_in; (void)out_size;
    const float* x  = (const float*)d_in[0];
    const float* qw = (const float*)d_in[1];
    const float* qb = (const float*)d_in[2];
    const float* kw = (const float*)d_in[3];
    const float* kb = (const float*)d_in[4];
    const float* vw = (const float*)d_in[5];
    const float* vb = (const float*)d_in[6];
    const float* cw = (const float*)d_in[7];
    const float* cb = (const float*)d_in[8];
    float* out = (float*)d_out;

    const int dsmem = 64 * 10 * 66 * sizeof(float);   // 168,960 B
    const int gsmem = 4 * (int)STAGE_B;               // 81,920 B
    cudaFuncSetAttribute(dwqk_kernel,      cudaFuncAttributeMaxDynamicSharedMemorySize, dsmem);
    cudaFuncSetAttribute(conv_gemm_kernel, cudaFuncAttributeMaxDynamicSharedMemorySize, CG_SMEM);
    cudaFuncSetAttribute(gemm_mma_kernel,  cudaFuncAttributeMaxDynamicSharedMemorySize, gsmem);

    // s0 (default): prep_w -> dwqk -> gemm0 -> softmax -> [join] gemm1 -> conv1
    // s1 (side)   :        \-> conv0 (V conv, independent of attention front-end)
    prep_w_kernel<<<(9 * 64 * 64 + 255) / 256, 256>>>(vw, cw);
    cudaEventRecord(g_ss.e0, 0);
    cudaStreamWaitEvent(g_ss.s1, g_ss.e0, 0);
    conv_gemm_kernel<<<dim3(64, 8), 512, CG_SMEM, g_ss.s1>>>(0, x, vb, nullptr);
    cudaEventRecord(g_ss.e1, g_ss.s1);

    dwqk_kernel<<<dim3(64, 8), 512, dsmem>>>(x, qw, qb, kw, kb);
    gemm_mma_kernel<<<dim3(8, 8, NB), 256, gsmem>>>(0);    // S = QK^T * scale
    softmax_kernel<<<NB * TOK, 128>>>();
    cudaStreamWaitEvent(0, g_ss.e1, 0);
    gemm_mma_kernel<<<dim3(32, 8, NB), 256, gsmem>>>(1);   // feat = fold(P V)
    conv_gemm_kernel<<<dim3(64, 8), 512, CG_SMEM>>>(1, x, cb, out);
}